// round 2
// baseline (speedup 1.0000x reference)
#include <cuda_runtime.h>
#include <math.h>

#define B_  2
#define S_  2048
#define E_  1024
#define H_  16
#define D_  64
#define E3_ 3072
#define M_  (B_ * S_)   // 4096

// Scratch (allocation-free rule: device globals)
__device__ float g_qkv[(size_t)M_ * E3_];   // [4096, 3072]  Q|K|V columns
__device__ float g_attn[(size_t)M_ * E_];   // [4096, 1024]  attention out, [b,s,h*d]

// ---------------------------------------------------------------------------
// Generic C[M,N] = A[M,K] * B[N,K]^T + bias[N]   (both operands K-major)
// 64x64 tile, BK=16, 256 threads, 4x4 microtile per thread.
// ---------------------------------------------------------------------------
__global__ __launch_bounds__(256) void sgemm_abt(
    const float* __restrict__ A, const float* __restrict__ Bw,
    const float* __restrict__ bias, float* __restrict__ C,
    int M, int N, int K)
{
    __shared__ float As[16][68];   // [k][m], pad to 68 for fp4 align + banks
    __shared__ float Bs[16][68];   // [k][n]

    const int tid = threadIdx.x;
    const int tx = tid & 15, ty = tid >> 4;
    const int m0 = blockIdx.y * 64;
    const int n0 = blockIdx.x * 64;

    const int lr = tid >> 2;          // 0..63  (row of tile)
    const int lc = (tid & 3) * 4;     // 0,4,8,12 (col4 within BK=16)

    float acc[4][4] = {};

    for (int kb = 0; kb < K; kb += 16) {
        float4 av = *(const float4*)&A [(size_t)(m0 + lr) * K + kb + lc];
        float4 bv = *(const float4*)&Bw[(size_t)(n0 + lr) * K + kb + lc];
        As[lc + 0][lr] = av.x; As[lc + 1][lr] = av.y;
        As[lc + 2][lr] = av.z; As[lc + 3][lr] = av.w;
        Bs[lc + 0][lr] = bv.x; Bs[lc + 1][lr] = bv.y;
        Bs[lc + 2][lr] = bv.z; Bs[lc + 3][lr] = bv.w;
        __syncthreads();

        #pragma unroll
        for (int kk = 0; kk < 16; kk++) {
            float4 a = *(const float4*)&As[kk][4 * ty];
            float4 b = *(const float4*)&Bs[kk][4 * tx];
            acc[0][0] += a.x * b.x; acc[0][1] += a.x * b.y;
            acc[0][2] += a.x * b.z; acc[0][3] += a.x * b.w;
            acc[1][0] += a.y * b.x; acc[1][1] += a.y * b.y;
            acc[1][2] += a.y * b.z; acc[1][3] += a.y * b.w;
            acc[2][0] += a.z * b.x; acc[2][1] += a.z * b.y;
            acc[2][2] += a.z * b.z; acc[2][3] += a.z * b.w;
            acc[3][0] += a.w * b.x; acc[3][1] += a.w * b.y;
            acc[3][2] += a.w * b.z; acc[3][3] += a.w * b.w;
        }
        __syncthreads();
    }

    const float4 bb = *(const float4*)&bias[n0 + 4 * tx];
    #pragma unroll
    for (int i = 0; i < 4; i++) {
        float4 o;
        o.x = acc[i][0] + bb.x; o.y = acc[i][1] + bb.y;
        o.z = acc[i][2] + bb.z; o.w = acc[i][3] + bb.w;
        *(float4*)&C[(size_t)(m0 + 4 * ty + i) * N + n0 + 4 * tx] = o;
    }
}

// ---------------------------------------------------------------------------
// Flash-style attention with multiplicative exponential distance decay.
// softmax( (Q K^T / sqrt(D)) * exp(-|a|*|i-j|) ) @ V
// Block: 64 queries x one (b,h). 256 threads, 4x4 microtiles. 32 key tiles.
// smem: Qs[64][68], Kt[64][68] (transposed), Vs[64][64], Ps[64][68] = 68.6KB
// ---------------------------------------------------------------------------
#define ATTN_SMEM_FLOATS (64 * 68 * 3 + 64 * 64)
#define ATTN_SMEM_BYTES  (ATTN_SMEM_FLOATS * 4)

__global__ __launch_bounds__(256) void attn_kernel(
    const float* __restrict__ qkv, const float* __restrict__ dd,
    float* __restrict__ attn_out)
{
    extern __shared__ float sm[];
    float* Qs = sm;                 // [64][68] row-major
    float* Kt = Qs + 64 * 68;       // [d][key] pad 68
    float* Vs = Kt + 64 * 68;       // [key][d] stride 64
    float* Ps = Vs + 64 * 64;       // [q][key] pad 68

    const int tid = threadIdx.x;
    const int tx = tid & 15, ty = tid >> 4;
    const int q0 = blockIdx.x * 64;
    const int h  = blockIdx.y;
    const int b  = blockIdx.z;

    const float na = fabsf(dd[0]);

    const float* Qg = qkv + (size_t)b * S_ * E3_ + h * D_;
    const float* Kg = Qg + E_;
    const float* Vg = Qg + 2 * E_;

    // Load Q tile (64 x 64)
    for (int t = tid; t < 1024; t += 256) {
        const int r = t >> 4, c4 = (t & 15) << 2;
        float4 v = *(const float4*)&Qg[(size_t)(q0 + r) * E3_ + c4];
        *(float4*)&Qs[r * 68 + c4] = v;
    }

    float m_i[4], l_i[4], acc[4][4];
    #pragma unroll
    for (int i = 0; i < 4; i++) {
        m_i[i] = -INFINITY; l_i[i] = 0.f;
        acc[i][0] = acc[i][1] = acc[i][2] = acc[i][3] = 0.f;
    }

    for (int k0 = 0; k0 < S_; k0 += 64) {
        __syncthreads();   // prev-iter readers of Kt/Vs/Ps done; Q load done
        // Load K tile transposed + V tile
        for (int t = tid; t < 1024; t += 256) {
            const int r = t >> 4, c4 = (t & 15) << 2;
            float4 kv = *(const float4*)&Kg[(size_t)(k0 + r) * E3_ + c4];
            Kt[(c4 + 0) * 68 + r] = kv.x;
            Kt[(c4 + 1) * 68 + r] = kv.y;
            Kt[(c4 + 2) * 68 + r] = kv.z;
            Kt[(c4 + 3) * 68 + r] = kv.w;
            float4 vv = *(const float4*)&Vg[(size_t)(k0 + r) * E3_ + c4];
            *(float4*)&Vs[r * 64 + c4] = vv;
        }
        __syncthreads();

        // S = Q K^T
        float s[4][4] = {};
        #pragma unroll 8
        for (int d = 0; d < 64; d++) {
            float4 kf = *(const float4*)&Kt[d * 68 + 4 * tx];
            const float qa = Qs[(4 * ty + 0) * 68 + d];
            const float qb = Qs[(4 * ty + 1) * 68 + d];
            const float qc = Qs[(4 * ty + 2) * 68 + d];
            const float qd = Qs[(4 * ty + 3) * 68 + d];
            s[0][0] += qa * kf.x; s[0][1] += qa * kf.y; s[0][2] += qa * kf.z; s[0][3] += qa * kf.w;
            s[1][0] += qb * kf.x; s[1][1] += qb * kf.y; s[1][2] += qb * kf.z; s[1][3] += qb * kf.w;
            s[2][0] += qc * kf.x; s[2][1] += qc * kf.y; s[2][2] += qc * kf.z; s[2][3] += qc * kf.w;
            s[3][0] += qd * kf.x; s[3][1] += qd * kf.y; s[3][2] += qd * kf.z; s[3][3] += qd * kf.w;
        }

        // scale + multiplicative decay, then online softmax
        #pragma unroll
        for (int i = 0; i < 4; i++) {
            const int qi = q0 + 4 * ty + i;
            #pragma unroll
            for (int j = 0; j < 4; j++) {
                const int kj = k0 + 4 * tx + j;
                const float dist = fabsf((float)(qi - kj));
                s[i][j] = s[i][j] * 0.125f * __expf(-na * dist);
            }
            float rm = fmaxf(fmaxf(s[i][0], s[i][1]), fmaxf(s[i][2], s[i][3]));
            rm = fmaxf(rm, __shfl_xor_sync(0xffffffffu, rm, 1));
            rm = fmaxf(rm, __shfl_xor_sync(0xffffffffu, rm, 2));
            rm = fmaxf(rm, __shfl_xor_sync(0xffffffffu, rm, 4));
            rm = fmaxf(rm, __shfl_xor_sync(0xffffffffu, rm, 8));
            const float mn = fmaxf(m_i[i], rm);
            const float scale = __expf(m_i[i] - mn);   // exp(-inf)=0 first iter
            float rs = 0.f;
            #pragma unroll
            for (int j = 0; j < 4; j++) {
                s[i][j] = __expf(s[i][j] - mn);
                rs += s[i][j];
            }
            rs += __shfl_xor_sync(0xffffffffu, rs, 1);
            rs += __shfl_xor_sync(0xffffffffu, rs, 2);
            rs += __shfl_xor_sync(0xffffffffu, rs, 4);
            rs += __shfl_xor_sync(0xffffffffu, rs, 8);
            l_i[i] = l_i[i] * scale + rs;
            m_i[i] = mn;
            acc[i][0] *= scale; acc[i][1] *= scale;
            acc[i][2] *= scale; acc[i][3] *= scale;
            float4 pv = make_float4(s[i][0], s[i][1], s[i][2], s[i][3]);
            *(float4*)&Ps[(4 * ty + i) * 68 + 4 * tx] = pv;
        }
        __syncthreads();

        // O += P V
        #pragma unroll 8
        for (int j = 0; j < 64; j++) {
            float4 vv = *(const float4*)&Vs[j * 64 + 4 * tx];
            const float pa = Ps[(4 * ty + 0) * 68 + j];
            const float pb = Ps[(4 * ty + 1) * 68 + j];
            const float pc = Ps[(4 * ty + 2) * 68 + j];
            const float pd = Ps[(4 * ty + 3) * 68 + j];
            acc[0][0] += pa * vv.x; acc[0][1] += pa * vv.y; acc[0][2] += pa * vv.z; acc[0][3] += pa * vv.w;
            acc[1][0] += pb * vv.x; acc[1][1] += pb * vv.y; acc[1][2] += pb * vv.z; acc[1][3] += pb * vv.w;
            acc[2][0] += pc * vv.x; acc[2][1] += pc * vv.y; acc[2][2] += pc * vv.z; acc[2][3] += pc * vv.w;
            acc[3][0] += pd * vv.x; acc[3][1] += pd * vv.y; acc[3][2] += pd * vv.z; acc[3][3] += pd * vv.w;
        }
    }

    // epilogue: divide by l, write [b, s, h*D + d]
    #pragma unroll
    for (int i = 0; i < 4; i++) {
        const float inv = 1.0f / l_i[i];
        float4 o = make_float4(acc[i][0] * inv, acc[i][1] * inv,
                               acc[i][2] * inv, acc[i][3] * inv);
        const size_t row = (size_t)(b * S_ + q0 + 4 * ty + i);
        *(float4*)&attn_out[row * E_ + h * D_ + 4 * tx] = o;
    }
}

// ---------------------------------------------------------------------------
extern "C" void kernel_launch(void* const* d_in, const int* in_sizes, int n_in,
                              void* d_out, int out_size)
{
    const float* x      = (const float*)d_in[0];  // [B,S,E]
    const float* Wqkv_w = (const float*)d_in[1];  // [3E,E]
    const float* Wqkv_b = (const float*)d_in[2];  // [3E]
    const float* out_w  = (const float*)d_in[3];  // [E,E]
    const float* out_b  = (const float*)d_in[4];  // [E]
    const float* dd     = (const float*)d_in[5];  // [1]
    float* out = (float*)d_out;

    float *qkv, *attn;
    cudaGetSymbolAddress((void**)&qkv, g_qkv);
    cudaGetSymbolAddress((void**)&attn, g_attn);

    // 1. QKV projection: [4096,3072] = x[4096,1024] @ Wqkv_w^T + b
    sgemm_abt<<<dim3(E3_ / 64, M_ / 64), 256>>>(x, Wqkv_w, Wqkv_b, qkv,
                                                M_, E3_, E_);

    // 2. attention
    cudaFuncSetAttribute(attn_kernel,
                         cudaFuncAttributeMaxDynamicSharedMemorySize,
                         ATTN_SMEM_BYTES);
    attn_kernel<<<dim3(S_ / 64, H_, B_), 256, ATTN_SMEM_BYTES>>>(qkv, dd, attn);

    // 3. output projection: [4096,1024] = attn @ out_w^T + out_b
    sgemm_abt<<<dim3(E_ / 64, M_ / 64), 256>>>(attn, out_w, out_b, out,
                                               M_, E_, E_);
}

// round 7
// speedup vs baseline: 1.8910x; 1.8910x over previous
#include <cuda_runtime.h>
#include <cuda_bf16.h>
#include <math.h>
#include <stdint.h>

#define B_  2
#define S_  2048
#define E_  1024
#define H_  16
#define D_  64
#define E3_ 3072
#define M_  (B_ * S_)   // 4096

// Scratch (allocation-free rule: device globals)
__device__ float g_qkv[(size_t)M_ * E3_];   // [4096, 3072]  Q|K|V columns
__device__ float g_attn[(size_t)M_ * E_];   // [4096, 1024]  attention out

// ===========================================================================
// mma.sync bf16 helper (baseline PTX, works on plain sm_103 target)
// D[16x8] += A[16x16] * B[16x8],  A row-major, B col-major (B[n][k] mem)
// ===========================================================================
__device__ __forceinline__ void mma16816(float* c, const uint32_t* a,
                                         const uint32_t* b) {
    asm volatile(
        "mma.sync.aligned.m16n8k16.row.col.f32.bf16.bf16.f32 "
        "{%0,%1,%2,%3}, {%4,%5,%6,%7}, {%8,%9}, {%0,%1,%2,%3};"
        : "+f"(c[0]), "+f"(c[1]), "+f"(c[2]), "+f"(c[3])
        : "r"(a[0]), "r"(a[1]), "r"(a[2]), "r"(a[3]), "r"(b[0]), "r"(b[1]));
}

__device__ __forceinline__ uint32_t pack_bf16(float a, float b) {
    __nv_bfloat162 h = __floats2bfloat162_rn(a, b);
    return *(uint32_t*)&h;
}

// ===========================================================================
// Split-bf16 tensor-core GEMM:  C[M,N] = A[M,K] * Bw[N,K]^T + bias[N]
// (unchanged from R5)
// ===========================================================================
#define GPAD 40

__global__ __launch_bounds__(256) void gemm_tc(
    const float* __restrict__ A, const float* __restrict__ Bw,
    const float* __restrict__ bias, float* __restrict__ C,
    int M, int N, int K)
{
    __shared__ __nv_bfloat16 Ah[128 * GPAD];
    __shared__ __nv_bfloat16 Al[128 * GPAD];
    __shared__ __nv_bfloat16 Bh[128 * GPAD];
    __shared__ __nv_bfloat16 Bl[128 * GPAD];

    const int tid = threadIdx.x;
    const int wid = tid >> 5;
    const int lid = tid & 31;
    const int gq  = lid >> 2;
    const int qt  = lid & 3;
    const int m0 = blockIdx.y * 128;
    const int n0 = blockIdx.x * 128;
    const int warpM = (wid >> 2) * 64;
    const int warpN = (wid & 3) * 32;

    float c[16][4];
    #pragma unroll
    for (int i = 0; i < 16; i++)
        c[i][0] = c[i][1] = c[i][2] = c[i][3] = 0.f;

    for (int kb = 0; kb < K; kb += 32) {
        __syncthreads();

        #pragma unroll
        for (int it = 0; it < 4; it++) {
            const int idx = tid + it * 256;
            const int row = idx >> 3;
            const int c4  = (idx & 7) << 2;
            const int so  = row * GPAD + c4;

            float4 v = *(const float4*)&A[(size_t)(m0 + row) * K + kb + c4];
            uint32_t h0 = pack_bf16(v.x, v.y);
            uint32_t h1 = pack_bf16(v.z, v.w);
            __nv_bfloat162 H0 = *(__nv_bfloat162*)&h0;
            __nv_bfloat162 H1 = *(__nv_bfloat162*)&h1;
            uint32_t l0 = pack_bf16(v.x - __bfloat162float(H0.x),
                                    v.y - __bfloat162float(H0.y));
            uint32_t l1 = pack_bf16(v.z - __bfloat162float(H1.x),
                                    v.w - __bfloat162float(H1.y));
            *(uint2*)&Ah[so] = make_uint2(h0, h1);
            *(uint2*)&Al[so] = make_uint2(l0, l1);

            float4 w = *(const float4*)&Bw[(size_t)(n0 + row) * K + kb + c4];
            uint32_t g0 = pack_bf16(w.x, w.y);
            uint32_t g1 = pack_bf16(w.z, w.w);
            __nv_bfloat162 G0 = *(__nv_bfloat162*)&g0;
            __nv_bfloat162 G1 = *(__nv_bfloat162*)&g1;
            uint32_t e0 = pack_bf16(w.x - __bfloat162float(G0.x),
                                    w.y - __bfloat162float(G0.y));
            uint32_t e1 = pack_bf16(w.z - __bfloat162float(G1.x),
                                    w.w - __bfloat162float(G1.y));
            *(uint2*)&Bh[so] = make_uint2(g0, g1);
            *(uint2*)&Bl[so] = make_uint2(e0, e1);
        }
        __syncthreads();

        #pragma unroll
        for (int kk = 0; kk < 2; kk++) {
            const int kcol = kk * 16 + qt * 2;
            uint32_t aH[4][4], bH[4][2], tA[4][4], tB[4][2];

            #pragma unroll
            for (int mt = 0; mt < 4; mt++) {
                const int r = warpM + mt * 16 + gq;
                aH[mt][0] = *(const uint32_t*)&Ah[r * GPAD + kcol];
                aH[mt][1] = *(const uint32_t*)&Ah[(r + 8) * GPAD + kcol];
                aH[mt][2] = *(const uint32_t*)&Ah[r * GPAD + kcol + 8];
                aH[mt][3] = *(const uint32_t*)&Ah[(r + 8) * GPAD + kcol + 8];
            }
            #pragma unroll
            for (int nt = 0; nt < 4; nt++) {
                const int r = warpN + nt * 8 + gq;
                bH[nt][0] = *(const uint32_t*)&Bh[r * GPAD + kcol];
                bH[nt][1] = *(const uint32_t*)&Bh[r * GPAD + kcol + 8];
            }
            #pragma unroll
            for (int mt = 0; mt < 4; mt++)
                #pragma unroll
                for (int nt = 0; nt < 4; nt++)
                    mma16816(c[mt * 4 + nt], aH[mt], bH[nt]);

            #pragma unroll
            for (int nt = 0; nt < 4; nt++) {
                const int r = warpN + nt * 8 + gq;
                tB[nt][0] = *(const uint32_t*)&Bl[r * GPAD + kcol];
                tB[nt][1] = *(const uint32_t*)&Bl[r * GPAD + kcol + 8];
            }
            #pragma unroll
            for (int mt = 0; mt < 4; mt++)
                #pragma unroll
                for (int nt = 0; nt < 4; nt++)
                    mma16816(c[mt * 4 + nt], aH[mt], tB[nt]);

            #pragma unroll
            for (int mt = 0; mt < 4; mt++) {
                const int r = warpM + mt * 16 + gq;
                tA[mt][0] = *(const uint32_t*)&Al[r * GPAD + kcol];
                tA[mt][1] = *(const uint32_t*)&Al[(r + 8) * GPAD + kcol];
                tA[mt][2] = *(const uint32_t*)&Al[r * GPAD + kcol + 8];
                tA[mt][3] = *(const uint32_t*)&Al[(r + 8) * GPAD + kcol + 8];
            }
            #pragma unroll
            for (int mt = 0; mt < 4; mt++)
                #pragma unroll
                for (int nt = 0; nt < 4; nt++)
                    mma16816(c[mt * 4 + nt], tA[mt], bH[nt]);
        }
    }

    #pragma unroll
    for (int mt = 0; mt < 4; mt++) {
        const int r0 = m0 + warpM + mt * 16 + gq;
        #pragma unroll
        for (int nt = 0; nt < 4; nt++) {
            const int col = n0 + warpN + nt * 8 + qt * 2;
            const float2 bb = *(const float2*)&bias[col];
            float* cc = c[mt * 4 + nt];
            *(float2*)&C[(size_t)r0 * N + col] =
                make_float2(cc[0] + bb.x, cc[1] + bb.y);
            *(float2*)&C[(size_t)(r0 + 8) * N + col] =
                make_float2(cc[2] + bb.x, cc[3] + bb.y);
        }
    }
}

// ===========================================================================
// Tensor-core flash attention with multiplicative exponential distance decay.
// softmax( (Q K^T / 8) * exp(-|a|*|i-j|) ) @ V
// CTA: 128 queries x one (b,h), 8 warps (16 query rows each), key tiles of 64.
// QK^T and PV on mma.sync bf16, 3-pass split precision. P stays in registers.
// Decay via smem lookup table over |i-j|.
// smem: Kh|Kl|Vth|Vtl 64x72 bf16 each (36864B; Q fp32 staging overlays it)
//       + decay table 2048 fp32 (8192B)  -> 45056B static.
// ===========================================================================
#define APAD 72    // bf16 row stride for K/Vt tiles
#define QPAD 68    // fp32 row stride for Q staging

__global__ __launch_bounds__(256, 1) void attn_tc(
    const float* __restrict__ qkv, const float* __restrict__ dd,
    float* __restrict__ attn_out)
{
    __shared__ __align__(16) char smraw[4 * 64 * APAD * 2];  // 36864
    __shared__ float dtab[2048];

    __nv_bfloat16* Kh  = (__nv_bfloat16*)smraw;
    __nv_bfloat16* Kl  = Kh + 64 * APAD;
    __nv_bfloat16* Vth = Kl + 64 * APAD;
    __nv_bfloat16* Vtl = Vth + 64 * APAD;
    float* Qs = (float*)smraw;                   // overlay, used pre-loop only

    const int tid = threadIdx.x;
    const int wid = tid >> 5;
    const int lid = tid & 31;
    const int gq  = lid >> 2;       // 0..7
    const int qt  = lid & 3;        // 0..3
    const int q0 = blockIdx.x * 128;
    const int h  = blockIdx.y;
    const int b  = blockIdx.z;

    const float na = fabsf(dd[0]);

    // decay table: exp(-|a| * dist)
    #pragma unroll
    for (int t = tid; t < 2048; t += 256)
        dtab[t] = __expf(-na * (float)t);

    const float* Qg = qkv + (size_t)b * S_ * E3_ + h * D_;
    const float* Kg = Qg + E_;
    const float* Vg = Qg + 2 * E_;

    // ---- stage Q tile (128x64 fp32) and build split fragments ----
    for (int t = tid; t < 2048; t += 256) {        // 128 rows x 16 float4
        const int r = t >> 4, c4 = (t & 15) << 2;
        float4 v = *(const float4*)&Qg[(size_t)(q0 + r) * E3_ + c4];
        *(float4*)&Qs[r * QPAD + c4] = v;
    }
    __syncthreads();

    uint32_t aQh[4][4], aQl[4][4];
    {
        const int r0 = wid * 16 + gq;
        #pragma unroll
        for (int kc = 0; kc < 4; kc++) {
            #pragma unroll
            for (int p = 0; p < 4; p++) {
                const int rr = r0 + ((p & 1) ? 8 : 0);
                const int cc = kc * 16 + qt * 2 + ((p & 2) ? 8 : 0);
                float2 f = *(const float2*)&Qs[rr * QPAD + cc];
                uint32_t hi = pack_bf16(f.x, f.y);
                __nv_bfloat162 H = *(__nv_bfloat162*)&hi;
                aQh[kc][p] = hi;
                aQl[kc][p] = pack_bf16(f.x - __bfloat162float(H.x),
                                       f.y - __bfloat162float(H.y));
            }
        }
    }
    __syncthreads();   // done with Qs overlay

    float m_i[2] = {-INFINITY, -INFINITY};
    float l_i[2] = {0.f, 0.f};
    float O[8][4];
    #pragma unroll
    for (int i = 0; i < 8; i++)
        O[i][0] = O[i][1] = O[i][2] = O[i][3] = 0.f;

    const int qrow0 = q0 + wid * 16 + gq;     // this thread's two rows: +0, +8

    for (int k0 = 0; k0 < S_; k0 += 64) {
        // ---- stage K (split) and V (transpose + split) ----
        #pragma unroll
        for (int it = 0; it < 4; it++) {
            const int idx = tid + it * 256;        // 0..1023
            const int r = idx >> 4;                // key row 0..63
            const int c4 = (idx & 15) << 2;        // d col 0..60
            float4 kv = *(const float4*)&Kg[(size_t)(k0 + r) * E3_ + c4];
            uint32_t h0 = pack_bf16(kv.x, kv.y);
            uint32_t h1 = pack_bf16(kv.z, kv.w);
            __nv_bfloat162 H0 = *(__nv_bfloat162*)&h0;
            __nv_bfloat162 H1 = *(__nv_bfloat162*)&h1;
            uint32_t l0 = pack_bf16(kv.x - __bfloat162float(H0.x),
                                    kv.y - __bfloat162float(H0.y));
            uint32_t l1 = pack_bf16(kv.z - __bfloat162float(H1.x),
                                    kv.w - __bfloat162float(H1.y));
            *(uint2*)&Kh[r * APAD + c4] = make_uint2(h0, h1);
            *(uint2*)&Kl[r * APAD + c4] = make_uint2(l0, l1);

            float4 vv = *(const float4*)&Vg[(size_t)(k0 + r) * E3_ + c4];
            const float vf[4] = {vv.x, vv.y, vv.z, vv.w};
            #pragma unroll
            for (int i = 0; i < 4; i++) {
                __nv_bfloat16 vh = __float2bfloat16_rn(vf[i]);
                Vth[(c4 + i) * APAD + r] = vh;
                Vtl[(c4 + i) * APAD + r] =
                    __float2bfloat16_rn(vf[i] - __bfloat162float(vh));
            }
        }
        __syncthreads();

        // ---- S = Q K^T  (split, 3 pass) ----
        float S[8][4];
        #pragma unroll
        for (int i = 0; i < 8; i++)
            S[i][0] = S[i][1] = S[i][2] = S[i][3] = 0.f;

        #pragma unroll
        for (int kc = 0; kc < 4; kc++) {
            #pragma unroll
            for (int nt = 0; nt < 8; nt++) {
                const int kr = nt * 8 + gq;
                const int cc = kc * 16 + qt * 2;
                uint32_t bh[2], bl[2];
                bh[0] = *(const uint32_t*)&Kh[kr * APAD + cc];
                bh[1] = *(const uint32_t*)&Kh[kr * APAD + cc + 8];
                bl[0] = *(const uint32_t*)&Kl[kr * APAD + cc];
                bl[1] = *(const uint32_t*)&Kl[kr * APAD + cc + 8];
                mma16816(S[nt], aQh[kc], bh);
                mma16816(S[nt], aQh[kc], bl);
                mma16816(S[nt], aQl[kc], bh);
            }
        }

        // ---- scale * decay, online softmax (rows owned by lane quads) ----
        float rm0 = -INFINITY, rm1 = -INFINITY;
        #pragma unroll
        for (int nt = 0; nt < 8; nt++) {
            const int kcol = k0 + nt * 8 + qt * 2;
            const float d00 = dtab[abs(qrow0 - kcol)];
            const float d01 = dtab[abs(qrow0 - kcol - 1)];
            const float d10 = dtab[abs(qrow0 + 8 - kcol)];
            const float d11 = dtab[abs(qrow0 + 8 - kcol - 1)];
            S[nt][0] *= 0.125f * d00;
            S[nt][1] *= 0.125f * d01;
            S[nt][2] *= 0.125f * d10;
            S[nt][3] *= 0.125f * d11;
            rm0 = fmaxf(rm0, fmaxf(S[nt][0], S[nt][1]));
            rm1 = fmaxf(rm1, fmaxf(S[nt][2], S[nt][3]));
        }
        rm0 = fmaxf(rm0, __shfl_xor_sync(0xffffffffu, rm0, 1));
        rm0 = fmaxf(rm0, __shfl_xor_sync(0xffffffffu, rm0, 2));
        rm1 = fmaxf(rm1, __shfl_xor_sync(0xffffffffu, rm1, 1));
        rm1 = fmaxf(rm1, __shfl_xor_sync(0xffffffffu, rm1, 2));

        const float mn0 = fmaxf(m_i[0], rm0);
        const float mn1 = fmaxf(m_i[1], rm1);
        const float sc0 = __expf(m_i[0] - mn0);
        const float sc1 = __expf(m_i[1] - mn1);

        float rs0 = 0.f, rs1 = 0.f;
        #pragma unroll
        for (int nt = 0; nt < 8; nt++) {
            S[nt][0] = __expf(S[nt][0] - mn0);
            S[nt][1] = __expf(S[nt][1] - mn0);
            S[nt][2] = __expf(S[nt][2] - mn1);
            S[nt][3] = __expf(S[nt][3] - mn1);
            rs0 += S[nt][0] + S[nt][1];
            rs1 += S[nt][2] + S[nt][3];
        }
        rs0 += __shfl_xor_sync(0xffffffffu, rs0, 1);
        rs0 += __shfl_xor_sync(0xffffffffu, rs0, 2);
        rs1 += __shfl_xor_sync(0xffffffffu, rs1, 1);
        rs1 += __shfl_xor_sync(0xffffffffu, rs1, 2);

        l_i[0] = l_i[0] * sc0 + rs0;
        l_i[1] = l_i[1] * sc1 + rs1;
        m_i[0] = mn0;
        m_i[1] = mn1;

        #pragma unroll
        for (int i = 0; i < 8; i++) {
            O[i][0] *= sc0; O[i][1] *= sc0;
            O[i][2] *= sc1; O[i][3] *= sc1;
        }

        // ---- pack P fragments (register-only, accum->A-frag layout) ----
        uint32_t aPh[4][4], aPl[4][4];
        #pragma unroll
        for (int j = 0; j < 4; j++) {
            const float* s0 = S[2 * j];
            const float* s1 = S[2 * j + 1];
            aPh[j][0] = pack_bf16(s0[0], s0[1]);
            aPh[j][1] = pack_bf16(s0[2], s0[3]);
            aPh[j][2] = pack_bf16(s1[0], s1[1]);
            aPh[j][3] = pack_bf16(s1[2], s1[3]);
            __nv_bfloat162 h0 = *(__nv_bfloat162*)&aPh[j][0];
            __nv_bfloat162 h1 = *(__nv_bfloat162*)&aPh[j][1];
            __nv_bfloat162 h2 = *(__nv_bfloat162*)&aPh[j][2];
            __nv_bfloat162 h3 = *(__nv_bfloat162*)&aPh[j][3];
            aPl[j][0] = pack_bf16(s0[0] - __bfloat162float(h0.x),
                                  s0[1] - __bfloat162float(h0.y));
            aPl[j][1] = pack_bf16(s0[2] - __bfloat162float(h1.x),
                                  s0[3] - __bfloat162float(h1.y));
            aPl[j][2] = pack_bf16(s1[0] - __bfloat162float(h2.x),
                                  s1[1] - __bfloat162float(h2.y));
            aPl[j][3] = pack_bf16(s1[2] - __bfloat162float(h3.x),
                                  s1[3] - __bfloat162float(h3.y));
        }

        // ---- O += P V  (split, 3 pass) ----
        #pragma unroll
        for (int j = 0; j < 4; j++) {
            #pragma unroll
            for (int nt = 0; nt < 8; nt++) {
                const int dr = nt * 8 + gq;
                const int cc = j * 16 + qt * 2;
                uint32_t vh[2], vl[2];
                vh[0] = *(const uint32_t*)&Vth[dr * APAD + cc];
                vh[1] = *(const uint32_t*)&Vth[dr * APAD + cc + 8];
                vl[0] = *(const uint32_t*)&Vtl[dr * APAD + cc];
                vl[1] = *(const uint32_t*)&Vtl[dr * APAD + cc + 8];
                mma16816(O[nt], aPh[j], vh);
                mma16816(O[nt], aPh[j], vl);
                mma16816(O[nt], aPl[j], vh);
            }
        }
        __syncthreads();   // all warps done with K/V tiles before restage
    }

    // ---- epilogue: O / l -> attn_out[b, s, h*64 + d] ----
    const float inv0 = 1.0f / l_i[0];
    const float inv1 = 1.0f / l_i[1];
    #pragma unroll
    for (int nt = 0; nt < 8; nt++) {
        const int col = h * D_ + nt * 8 + qt * 2;
        const size_t r0 = (size_t)(b * S_ + qrow0);
        *(float2*)&attn_out[r0 * E_ + col] =
            make_float2(O[nt][0] * inv0, O[nt][1] * inv0);
        *(float2*)&attn_out[(r0 + 8) * E_ + col] =
            make_float2(O[nt][2] * inv1, O[nt][3] * inv1);
    }
}

// ===========================================================================
extern "C" void kernel_launch(void* const* d_in, const int* in_sizes, int n_in,
                              void* d_out, int out_size)
{
    const float* x      = (const float*)d_in[0];
    const float* Wqkv_w = (const float*)d_in[1];
    const float* Wqkv_b = (const float*)d_in[2];
    const float* out_w  = (const float*)d_in[3];
    const float* out_b  = (const float*)d_in[4];
    const float* dd     = (const float*)d_in[5];
    float* out = (float*)d_out;

    float *qkv, *attn;
    cudaGetSymbolAddress((void**)&qkv, g_qkv);
    cudaGetSymbolAddress((void**)&attn, g_attn);

    // 1. QKV projection: [4096,3072] = x @ Wqkv_w^T + b  (split-bf16 HMMA)
    gemm_tc<<<dim3(E3_ / 128, M_ / 128), 256>>>(x, Wqkv_w, Wqkv_b, qkv,
                                                M_, E3_, E_);

    // 2. attention (tensor-core flash, split-bf16)
    attn_tc<<<dim3(S_ / 128, H_, B_), 256>>>(qkv, dd, attn);

    // 3. output projection: [4096,1024] = attn @ out_w^T + out_b
    gemm_tc<<<dim3(E_ / 128, M_ / 128), 256>>>(attn, out_w, out_b, out,
                                               M_, E_, E_);
}

// round 8
// speedup vs baseline: 2.3065x; 1.2197x over previous
#include <cuda_runtime.h>
#include <cuda_bf16.h>
#include <math.h>
#include <stdint.h>

#define B_  2
#define S_  2048
#define E_  1024
#define H_  16
#define D_  64
#define E3_ 3072
#define M_  (B_ * S_)   // 4096

// Scratch (allocation-free rule: device globals)
__device__ float g_qkv[(size_t)M_ * E3_];   // [4096, 3072]  Q|K|V columns
__device__ float g_attn[(size_t)M_ * E_];   // [4096, 1024]  attention out

// ===========================================================================
// mma.sync bf16 helper (baseline PTX, works on plain sm_103 target)
// D[16x8] += A[16x16] * B[16x8],  A row-major, B col-major (B[n][k] mem)
// ===========================================================================
__device__ __forceinline__ void mma16816(float* c, const uint32_t* a,
                                         const uint32_t* b) {
    asm volatile(
        "mma.sync.aligned.m16n8k16.row.col.f32.bf16.bf16.f32 "
        "{%0,%1,%2,%3}, {%4,%5,%6,%7}, {%8,%9}, {%0,%1,%2,%3};"
        : "+f"(c[0]), "+f"(c[1]), "+f"(c[2]), "+f"(c[3])
        : "r"(a[0]), "r"(a[1]), "r"(a[2]), "r"(a[3]), "r"(b[0]), "r"(b[1]));
}

__device__ __forceinline__ uint32_t pack_bf16(float a, float b) {
    __nv_bfloat162 h = __floats2bfloat162_rn(a, b);
    return *(uint32_t*)&h;
}

// ===========================================================================
// Split-bf16 tensor-core GEMM with register-prefetch pipelining.
// C[M,N] = A[M,K] * Bw[N,K]^T + bias[N]
// ===========================================================================
#define GPAD 40

__global__ __launch_bounds__(256) void gemm_tc(
    const float* __restrict__ A, const float* __restrict__ Bw,
    const float* __restrict__ bias, float* __restrict__ C,
    int M, int N, int K)
{
    __shared__ __nv_bfloat16 Ah[128 * GPAD];
    __shared__ __nv_bfloat16 Al[128 * GPAD];
    __shared__ __nv_bfloat16 Bh[128 * GPAD];
    __shared__ __nv_bfloat16 Bl[128 * GPAD];

    const int tid = threadIdx.x;
    const int wid = tid >> 5;
    const int lid = tid & 31;
    const int gq  = lid >> 2;
    const int qt  = lid & 3;
    const int m0 = blockIdx.y * 128;
    const int n0 = blockIdx.x * 128;
    const int warpM = (wid >> 2) * 64;
    const int warpN = (wid & 3) * 32;

    // per-thread staging coordinates (4 float4 per operand)
    int srow[4], scol[4];
    #pragma unroll
    for (int it = 0; it < 4; it++) {
        const int idx = tid + it * 256;
        srow[it] = idx >> 3;
        scol[it] = (idx & 7) << 2;
    }

    float c[16][4];
    #pragma unroll
    for (int i = 0; i < 16; i++)
        c[i][0] = c[i][1] = c[i][2] = c[i][3] = 0.f;

    // prologue: prefetch k-chunk 0
    float4 pA[4], pB[4];
    #pragma unroll
    for (int it = 0; it < 4; it++) {
        pA[it] = *(const float4*)&A [(size_t)(m0 + srow[it]) * K + scol[it]];
        pB[it] = *(const float4*)&Bw[(size_t)(n0 + srow[it]) * K + scol[it]];
    }

    for (int kb = 0; kb < K; kb += 32) {
        // convert + store the prefetched chunk
        #pragma unroll
        for (int it = 0; it < 4; it++) {
            const int so = srow[it] * GPAD + scol[it];

            float4 v = pA[it];
            uint32_t h0 = pack_bf16(v.x, v.y);
            uint32_t h1 = pack_bf16(v.z, v.w);
            __nv_bfloat162 H0 = *(__nv_bfloat162*)&h0;
            __nv_bfloat162 H1 = *(__nv_bfloat162*)&h1;
            uint32_t l0 = pack_bf16(v.x - __bfloat162float(H0.x),
                                    v.y - __bfloat162float(H0.y));
            uint32_t l1 = pack_bf16(v.z - __bfloat162float(H1.x),
                                    v.w - __bfloat162float(H1.y));
            *(uint2*)&Ah[so] = make_uint2(h0, h1);
            *(uint2*)&Al[so] = make_uint2(l0, l1);

            float4 w = pB[it];
            uint32_t g0 = pack_bf16(w.x, w.y);
            uint32_t g1 = pack_bf16(w.z, w.w);
            __nv_bfloat162 G0 = *(__nv_bfloat162*)&g0;
            __nv_bfloat162 G1 = *(__nv_bfloat162*)&g1;
            uint32_t e0 = pack_bf16(w.x - __bfloat162float(G0.x),
                                    w.y - __bfloat162float(G0.y));
            uint32_t e1 = pack_bf16(w.z - __bfloat162float(G1.x),
                                    w.w - __bfloat162float(G1.y));
            *(uint2*)&Bh[so] = make_uint2(g0, g1);
            *(uint2*)&Bl[so] = make_uint2(e0, e1);
        }
        __syncthreads();

        // prefetch next chunk (LDGs overlap the MMA phase below)
        const int kn = (kb + 32 < K) ? kb + 32 : 0;   // clamped; dummy on last
        #pragma unroll
        for (int it = 0; it < 4; it++) {
            pA[it] = *(const float4*)&A [(size_t)(m0 + srow[it]) * K + kn + scol[it]];
            pB[it] = *(const float4*)&Bw[(size_t)(n0 + srow[it]) * K + kn + scol[it]];
        }

        #pragma unroll
        for (int kk = 0; kk < 2; kk++) {
            const int kcol = kk * 16 + qt * 2;
            uint32_t aH[4][4], bH[4][2], tA[4][4], tB[4][2];

            #pragma unroll
            for (int mt = 0; mt < 4; mt++) {
                const int r = warpM + mt * 16 + gq;
                aH[mt][0] = *(const uint32_t*)&Ah[r * GPAD + kcol];
                aH[mt][1] = *(const uint32_t*)&Ah[(r + 8) * GPAD + kcol];
                aH[mt][2] = *(const uint32_t*)&Ah[r * GPAD + kcol + 8];
                aH[mt][3] = *(const uint32_t*)&Ah[(r + 8) * GPAD + kcol + 8];
            }
            #pragma unroll
            for (int nt = 0; nt < 4; nt++) {
                const int r = warpN + nt * 8 + gq;
                bH[nt][0] = *(const uint32_t*)&Bh[r * GPAD + kcol];
                bH[nt][1] = *(const uint32_t*)&Bh[r * GPAD + kcol + 8];
            }
            #pragma unroll
            for (int mt = 0; mt < 4; mt++)
                #pragma unroll
                for (int nt = 0; nt < 4; nt++)
                    mma16816(c[mt * 4 + nt], aH[mt], bH[nt]);

            #pragma unroll
            for (int nt = 0; nt < 4; nt++) {
                const int r = warpN + nt * 8 + gq;
                tB[nt][0] = *(const uint32_t*)&Bl[r * GPAD + kcol];
                tB[nt][1] = *(const uint32_t*)&Bl[r * GPAD + kcol + 8];
            }
            #pragma unroll
            for (int mt = 0; mt < 4; mt++)
                #pragma unroll
                for (int nt = 0; nt < 4; nt++)
                    mma16816(c[mt * 4 + nt], aH[mt], tB[nt]);

            #pragma unroll
            for (int mt = 0; mt < 4; mt++) {
                const int r = warpM + mt * 16 + gq;
                tA[mt][0] = *(const uint32_t*)&Al[r * GPAD + kcol];
                tA[mt][1] = *(const uint32_t*)&Al[(r + 8) * GPAD + kcol];
                tA[mt][2] = *(const uint32_t*)&Al[r * GPAD + kcol + 8];
                tA[mt][3] = *(const uint32_t*)&Al[(r + 8) * GPAD + kcol + 8];
            }
            #pragma unroll
            for (int mt = 0; mt < 4; mt++)
                #pragma unroll
                for (int nt = 0; nt < 4; nt++)
                    mma16816(c[mt * 4 + nt], tA[mt], bH[nt]);
        }
        __syncthreads();
    }

    #pragma unroll
    for (int mt = 0; mt < 4; mt++) {
        const int r0 = m0 + warpM + mt * 16 + gq;
        #pragma unroll
        for (int nt = 0; nt < 4; nt++) {
            const int col = n0 + warpN + nt * 8 + qt * 2;
            const float2 bb = *(const float2*)&bias[col];
            float* cc = c[mt * 4 + nt];
            *(float2*)&C[(size_t)r0 * N + col] =
                make_float2(cc[0] + bb.x, cc[1] + bb.y);
            *(float2*)&C[(size_t)(r0 + 8) * N + col] =
                make_float2(cc[2] + bb.x, cc[3] + bb.y);
        }
    }
}

// ===========================================================================
// Tensor-core flash attention, register-prefetch K/V staging + swizzled Vt.
// Vt element (d,t) stored at column t ^ (((d>>2)&3)<<1): store conflicts
// 8-way -> 2-way; fragment loads remain conflict-free.
// ===========================================================================
#define APAD 72    // bf16 row stride for K/Vt tiles
#define QPAD 68    // fp32 row stride for Q staging

__global__ __launch_bounds__(256, 1) void attn_tc(
    const float* __restrict__ qkv, const float* __restrict__ dd,
    float* __restrict__ attn_out)
{
    __shared__ __align__(16) char smraw[4 * 64 * APAD * 2];  // 36864
    __shared__ float dtab[2048];

    __nv_bfloat16* Kh  = (__nv_bfloat16*)smraw;
    __nv_bfloat16* Kl  = Kh + 64 * APAD;
    __nv_bfloat16* Vth = Kl + 64 * APAD;
    __nv_bfloat16* Vtl = Vth + 64 * APAD;
    float* Qs = (float*)smraw;                   // overlay, used pre-loop only

    const int tid = threadIdx.x;
    const int wid = tid >> 5;
    const int lid = tid & 31;
    const int gq  = lid >> 2;
    const int qt  = lid & 3;
    const int q0 = blockIdx.x * 128;
    const int h  = blockIdx.y;
    const int b  = blockIdx.z;

    const float na = fabsf(dd[0]);

    #pragma unroll
    for (int t = tid; t < 2048; t += 256)
        dtab[t] = __expf(-na * (float)t);

    const float* Qg = qkv + (size_t)b * S_ * E3_ + h * D_;
    const float* Kg = Qg + E_;
    const float* Vg = Qg + 2 * E_;

    // staging coordinates (4 float4 per tile per operand)
    int krow[4], kcol4[4];
    #pragma unroll
    for (int it = 0; it < 4; it++) {
        const int idx = tid + it * 256;
        krow[it]  = idx >> 4;          // key row 0..63
        kcol4[it] = (idx & 15) << 2;   // d col 0..60
    }

    // ---- stage Q tile and build split fragments ----
    for (int t = tid; t < 2048; t += 256) {
        const int r = t >> 4, c4 = (t & 15) << 2;
        float4 v = *(const float4*)&Qg[(size_t)(q0 + r) * E3_ + c4];
        *(float4*)&Qs[r * QPAD + c4] = v;
    }
    __syncthreads();

    uint32_t aQh[4][4], aQl[4][4];
    {
        const int r0 = wid * 16 + gq;
        #pragma unroll
        for (int kc = 0; kc < 4; kc++) {
            #pragma unroll
            for (int p = 0; p < 4; p++) {
                const int rr = r0 + ((p & 1) ? 8 : 0);
                const int cc = kc * 16 + qt * 2 + ((p & 2) ? 8 : 0);
                float2 f = *(const float2*)&Qs[rr * QPAD + cc];
                uint32_t hi = pack_bf16(f.x, f.y);
                __nv_bfloat162 H = *(__nv_bfloat162*)&hi;
                aQh[kc][p] = hi;
                aQl[kc][p] = pack_bf16(f.x - __bfloat162float(H.x),
                                       f.y - __bfloat162float(H.y));
            }
        }
    }
    __syncthreads();   // done with Qs overlay

    float m_i[2] = {-INFINITY, -INFINITY};
    float l_i[2] = {0.f, 0.f};
    float O[8][4];
    #pragma unroll
    for (int i = 0; i < 8; i++)
        O[i][0] = O[i][1] = O[i][2] = O[i][3] = 0.f;

    const int qrow0 = q0 + wid * 16 + gq;

    // prologue: prefetch K/V tile 0
    float4 pK[4], pV[4];
    #pragma unroll
    for (int it = 0; it < 4; it++) {
        pK[it] = *(const float4*)&Kg[(size_t)krow[it] * E3_ + kcol4[it]];
        pV[it] = *(const float4*)&Vg[(size_t)krow[it] * E3_ + kcol4[it]];
    }

    for (int k0 = 0; k0 < S_; k0 += 64) {
        // ---- convert + store prefetched K (split) and V (transpose+split) ----
        #pragma unroll
        for (int it = 0; it < 4; it++) {
            const int r  = krow[it];
            const int c4 = kcol4[it];

            float4 kv = pK[it];
            uint32_t h0 = pack_bf16(kv.x, kv.y);
            uint32_t h1 = pack_bf16(kv.z, kv.w);
            __nv_bfloat162 H0 = *(__nv_bfloat162*)&h0;
            __nv_bfloat162 H1 = *(__nv_bfloat162*)&h1;
            uint32_t l0 = pack_bf16(kv.x - __bfloat162float(H0.x),
                                    kv.y - __bfloat162float(H0.y));
            uint32_t l1 = pack_bf16(kv.z - __bfloat162float(H1.x),
                                    kv.w - __bfloat162float(H1.y));
            *(uint2*)&Kh[r * APAD + c4] = make_uint2(h0, h1);
            *(uint2*)&Kl[r * APAD + c4] = make_uint2(l0, l1);

            float4 vv = pV[it];
            const float vf[4] = {vv.x, vv.y, vv.z, vv.w};
            const int sw = ((c4 >> 2) & 3) << 1;      // same for all 4 d here
            const int tcol = r ^ sw;
            #pragma unroll
            for (int i = 0; i < 4; i++) {
                __nv_bfloat16 vh = __float2bfloat16_rn(vf[i]);
                Vth[(c4 + i) * APAD + tcol] = vh;
                Vtl[(c4 + i) * APAD + tcol] =
                    __float2bfloat16_rn(vf[i] - __bfloat162float(vh));
            }
        }
        __syncthreads();

        // prefetch next K/V tile (overlaps the whole compute phase)
        const int knext = (k0 + 64 < S_) ? k0 + 64 : 0;
        #pragma unroll
        for (int it = 0; it < 4; it++) {
            pK[it] = *(const float4*)&Kg[(size_t)(knext + krow[it]) * E3_ + kcol4[it]];
            pV[it] = *(const float4*)&Vg[(size_t)(knext + krow[it]) * E3_ + kcol4[it]];
        }

        // ---- S = Q K^T  (split, 3 pass) ----
        float S[8][4];
        #pragma unroll
        for (int i = 0; i < 8; i++)
            S[i][0] = S[i][1] = S[i][2] = S[i][3] = 0.f;

        #pragma unroll
        for (int kc = 0; kc < 4; kc++) {
            #pragma unroll
            for (int nt = 0; nt < 8; nt++) {
                const int kr = nt * 8 + gq;
                const int cc = kc * 16 + qt * 2;
                uint32_t bh[2], bl[2];
                bh[0] = *(const uint32_t*)&Kh[kr * APAD + cc];
                bh[1] = *(const uint32_t*)&Kh[kr * APAD + cc + 8];
                bl[0] = *(const uint32_t*)&Kl[kr * APAD + cc];
                bl[1] = *(const uint32_t*)&Kl[kr * APAD + cc + 8];
                mma16816(S[nt], aQh[kc], bh);
                mma16816(S[nt], aQh[kc], bl);
                mma16816(S[nt], aQl[kc], bh);
            }
        }

        // ---- scale * decay, online softmax ----
        float rm0 = -INFINITY, rm1 = -INFINITY;
        #pragma unroll
        for (int nt = 0; nt < 8; nt++) {
            const int kcol = k0 + nt * 8 + qt * 2;
            const float d00 = dtab[abs(qrow0 - kcol)];
            const float d01 = dtab[abs(qrow0 - kcol - 1)];
            const float d10 = dtab[abs(qrow0 + 8 - kcol)];
            const float d11 = dtab[abs(qrow0 + 8 - kcol - 1)];
            S[nt][0] *= 0.125f * d00;
            S[nt][1] *= 0.125f * d01;
            S[nt][2] *= 0.125f * d10;
            S[nt][3] *= 0.125f * d11;
            rm0 = fmaxf(rm0, fmaxf(S[nt][0], S[nt][1]));
            rm1 = fmaxf(rm1, fmaxf(S[nt][2], S[nt][3]));
        }
        rm0 = fmaxf(rm0, __shfl_xor_sync(0xffffffffu, rm0, 1));
        rm0 = fmaxf(rm0, __shfl_xor_sync(0xffffffffu, rm0, 2));
        rm1 = fmaxf(rm1, __shfl_xor_sync(0xffffffffu, rm1, 1));
        rm1 = fmaxf(rm1, __shfl_xor_sync(0xffffffffu, rm1, 2));

        const float mn0 = fmaxf(m_i[0], rm0);
        const float mn1 = fmaxf(m_i[1], rm1);
        const float sc0 = __expf(m_i[0] - mn0);
        const float sc1 = __expf(m_i[1] - mn1);

        float rs0 = 0.f, rs1 = 0.f;
        #pragma unroll
        for (int nt = 0; nt < 8; nt++) {
            S[nt][0] = __expf(S[nt][0] - mn0);
            S[nt][1] = __expf(S[nt][1] - mn0);
            S[nt][2] = __expf(S[nt][2] - mn1);
            S[nt][3] = __expf(S[nt][3] - mn1);
            rs0 += S[nt][0] + S[nt][1];
            rs1 += S[nt][2] + S[nt][3];
        }
        rs0 += __shfl_xor_sync(0xffffffffu, rs0, 1);
        rs0 += __shfl_xor_sync(0xffffffffu, rs0, 2);
        rs1 += __shfl_xor_sync(0xffffffffu, rs1, 1);
        rs1 += __shfl_xor_sync(0xffffffffu, rs1, 2);

        l_i[0] = l_i[0] * sc0 + rs0;
        l_i[1] = l_i[1] * sc1 + rs1;
        m_i[0] = mn0;
        m_i[1] = mn1;

        #pragma unroll
        for (int i = 0; i < 8; i++) {
            O[i][0] *= sc0; O[i][1] *= sc0;
            O[i][2] *= sc1; O[i][3] *= sc1;
        }

        // ---- pack P fragments (register-only) ----
        uint32_t aPh[4][4], aPl[4][4];
        #pragma unroll
        for (int j = 0; j < 4; j++) {
            const float* s0 = S[2 * j];
            const float* s1 = S[2 * j + 1];
            aPh[j][0] = pack_bf16(s0[0], s0[1]);
            aPh[j][1] = pack_bf16(s0[2], s0[3]);
            aPh[j][2] = pack_bf16(s1[0], s1[1]);
            aPh[j][3] = pack_bf16(s1[2], s1[3]);
            __nv_bfloat162 h0 = *(__nv_bfloat162*)&aPh[j][0];
            __nv_bfloat162 h1 = *(__nv_bfloat162*)&aPh[j][1];
            __nv_bfloat162 h2 = *(__nv_bfloat162*)&aPh[j][2];
            __nv_bfloat162 h3 = *(__nv_bfloat162*)&aPh[j][3];
            aPl[j][0] = pack_bf16(s0[0] - __bfloat162float(h0.x),
                                  s0[1] - __bfloat162float(h0.y));
            aPl[j][1] = pack_bf16(s0[2] - __bfloat162float(h1.x),
                                  s0[3] - __bfloat162float(h1.y));
            aPl[j][2] = pack_bf16(s1[0] - __bfloat162float(h2.x),
                                  s1[1] - __bfloat162float(h2.y));
            aPl[j][3] = pack_bf16(s1[2] - __bfloat162float(h3.x),
                                  s1[3] - __bfloat162float(h3.y));
        }

        // ---- O += P V  (split, 3 pass; swizzled Vt columns) ----
        #pragma unroll
        for (int j = 0; j < 4; j++) {
            #pragma unroll
            for (int nt = 0; nt < 8; nt++) {
                const int dr = nt * 8 + gq;
                const int sw = ((dr >> 2) & 3) << 1;
                const int cc = (j * 16 + qt * 2) ^ sw;
                uint32_t vh[2], vl[2];
                vh[0] = *(const uint32_t*)&Vth[dr * APAD + cc];
                vh[1] = *(const uint32_t*)&Vth[dr * APAD + cc + 8];
                vl[0] = *(const uint32_t*)&Vtl[dr * APAD + cc];
                vl[1] = *(const uint32_t*)&Vtl[dr * APAD + cc + 8];
                mma16816(O[nt], aPh[j], vh);
                mma16816(O[nt], aPh[j], vl);
                mma16816(O[nt], aPl[j], vh);
            }
        }
        __syncthreads();
    }

    // ---- epilogue ----
    const float inv0 = 1.0f / l_i[0];
    const float inv1 = 1.0f / l_i[1];
    #pragma unroll
    for (int nt = 0; nt < 8; nt++) {
        const int col = h * D_ + nt * 8 + qt * 2;
        const size_t r0 = (size_t)(b * S_ + qrow0);
        *(float2*)&attn_out[r0 * E_ + col] =
            make_float2(O[nt][0] * inv0, O[nt][1] * inv0);
        *(float2*)&attn_out[(r0 + 8) * E_ + col] =
            make_float2(O[nt][2] * inv1, O[nt][3] * inv1);
    }
}

// ===========================================================================
extern "C" void kernel_launch(void* const* d_in, const int* in_sizes, int n_in,
                              void* d_out, int out_size)
{
    const float* x      = (const float*)d_in[0];
    const float* Wqkv_w = (const float*)d_in[1];
    const float* Wqkv_b = (const float*)d_in[2];
    const float* out_w  = (const float*)d_in[3];
    const float* out_b  = (const float*)d_in[4];
    const float* dd     = (const float*)d_in[5];
    float* out = (float*)d_out;

    float *qkv, *attn;
    cudaGetSymbolAddress((void**)&qkv, g_qkv);
    cudaGetSymbolAddress((void**)&attn, g_attn);

    // 1. QKV projection (split-bf16 HMMA, pipelined)
    gemm_tc<<<dim3(E3_ / 128, M_ / 128), 256>>>(x, Wqkv_w, Wqkv_b, qkv,
                                                M_, E3_, E_);

    // 2. attention (tensor-core flash, pipelined staging)
    attn_tc<<<dim3(S_ / 128, H_, B_), 256>>>(qkv, dd, attn);

    // 3. output projection
    gemm_tc<<<dim3(E_ / 128, M_ / 128), 256>>>(attn, out_w, out_b, out,
                                               M_, E_, E_);
}

// round 9
// speedup vs baseline: 2.7166x; 1.1778x over previous
#include <cuda_runtime.h>
#include <cuda_bf16.h>
#include <math.h>
#include <stdint.h>

#define B_  2
#define S_  2048
#define E_  1024
#define H_  16
#define D_  64
#define E3_ 3072
#define M_  (B_ * S_)   // 4096

// ---------------- device-global scratch (allocation-free rule) -------------
__device__ __nv_bfloat16 g_xh [(size_t)M_  * E_ ], g_xl [(size_t)M_  * E_ ];
__device__ __nv_bfloat16 g_wqh[(size_t)E3_ * E_ ], g_wql[(size_t)E3_ * E_ ];
__device__ __nv_bfloat16 g_owh[(size_t)E_  * E_ ], g_owl[(size_t)E_  * E_ ];
__device__ __nv_bfloat16 g_qkvh[(size_t)M_ * E3_], g_qkvl[(size_t)M_ * E3_];
__device__ __nv_bfloat16 g_ath[(size_t)M_  * E_ ], g_atl[(size_t)M_  * E_ ];

// ---------------- PTX helpers (baseline ISA only) --------------------------
__device__ __forceinline__ void mma16816(float* c, const uint32_t* a,
                                         const uint32_t* b) {
    asm volatile(
        "mma.sync.aligned.m16n8k16.row.col.f32.bf16.bf16.f32 "
        "{%0,%1,%2,%3}, {%4,%5,%6,%7}, {%8,%9}, {%0,%1,%2,%3};"
        : "+f"(c[0]), "+f"(c[1]), "+f"(c[2]), "+f"(c[3])
        : "r"(a[0]), "r"(a[1]), "r"(a[2]), "r"(a[3]), "r"(b[0]), "r"(b[1]));
}

__device__ __forceinline__ uint32_t pack_bf16(float a, float b) {
    __nv_bfloat162 h = __floats2bfloat162_rn(a, b);
    return *(uint32_t*)&h;
}

__device__ __forceinline__ uint32_t smem_u32(const void* p) {
    uint32_t a;
    asm("{ .reg .u64 t; cvta.to.shared.u64 t, %1; cvt.u32.u64 %0, t; }"
        : "=r"(a) : "l"(p));
    return a;
}

__device__ __forceinline__ void cp_async16(uint32_t dst, const void* src) {
    asm volatile("cp.async.ca.shared.global [%0], [%1], 16;"
                 :: "r"(dst), "l"(src));
}
#define CP_COMMIT() asm volatile("cp.async.commit_group;" ::: "memory")
#define CP_WAIT_1() asm volatile("cp.async.wait_group 1;" ::: "memory")
#define CP_WAIT_0() asm volatile("cp.async.wait_group 0;" ::: "memory")

__device__ __forceinline__ void ldsm4t(uint32_t* r, uint32_t addr) {
    asm volatile(
        "ldmatrix.sync.aligned.m8n8.x4.trans.shared.b16 {%0,%1,%2,%3}, [%4];"
        : "=r"(r[0]), "=r"(r[1]), "=r"(r[2]), "=r"(r[3]) : "r"(addr));
}

// ---------------- split fp32 -> bf16 hi/lo ---------------------------------
__global__ __launch_bounds__(256) void split_bf16(
    const float* __restrict__ src, __nv_bfloat16* __restrict__ hi,
    __nv_bfloat16* __restrict__ lo, int n4)
{
    const int i = blockIdx.x * 256 + threadIdx.x;
    if (i >= n4) return;
    float4 v = ((const float4*)src)[i];
    uint32_t h0 = pack_bf16(v.x, v.y);
    uint32_t h1 = pack_bf16(v.z, v.w);
    __nv_bfloat162 H0 = *(__nv_bfloat162*)&h0;
    __nv_bfloat162 H1 = *(__nv_bfloat162*)&h1;
    uint32_t l0 = pack_bf16(v.x - __bfloat162float(H0.x),
                            v.y - __bfloat162float(H0.y));
    uint32_t l1 = pack_bf16(v.z - __bfloat162float(H1.x),
                            v.w - __bfloat162float(H1.y));
    ((uint2*)hi)[i] = make_uint2(h0, h1);
    ((uint2*)lo)[i] = make_uint2(l0, l1);
}

// ===========================================================================
// Split-bf16 HMMA GEMM, pre-split operands, cp.async double-buffered.
// C = A[M,K] * B[N,K]^T + bias.  Output: fp32 (Cf) or split bf16 (Ch/Cl).
// ===========================================================================
#define GPAD 40
#define GARR (128 * GPAD)          // 5120 el per array
#define GSTAGE (4 * GARR)          // elements per stage (20480 el, 40960 B)
#define GEMM_SMEM (2 * GSTAGE * 2) // bytes

__global__ __launch_bounds__(256, 2) void gemm_tc(
    const __nv_bfloat16* __restrict__ Ahg, const __nv_bfloat16* __restrict__ Alg,
    const __nv_bfloat16* __restrict__ Bhg, const __nv_bfloat16* __restrict__ Blg,
    const float* __restrict__ bias,
    float* __restrict__ Cf, __nv_bfloat16* __restrict__ Ch,
    __nv_bfloat16* __restrict__ Cl,
    int M, int N, int K)
{
    extern __shared__ __nv_bfloat16 sm[];
    const uint32_t smb = smem_u32(sm);

    const int tid = threadIdx.x;
    const int wid = tid >> 5;
    const int lid = tid & 31;
    const int gq  = lid >> 2;
    const int qt  = lid & 3;
    const int m0 = blockIdx.y * 128;
    const int n0 = blockIdx.x * 128;
    const int warpM = (wid >> 2) * 64;
    const int warpN = (wid & 3) * 32;

    float c[16][4];
    #pragma unroll
    for (int i = 0; i < 16; i++)
        c[i][0] = c[i][1] = c[i][2] = c[i][3] = 0.f;

    // staging: 512 16B-chunks per array, 2 per thread per array
    const int r0s = (tid + 0)   >> 2, g0s = (tid & 3) * 8;
    const int r1s = (tid + 256) >> 2, g1s = g0s;          // idx&3 same

    auto stage = [&](int s, int kb) {
        const uint32_t base = smb + (uint32_t)(s * GSTAGE) * 2;
        // chunk 0
        cp_async16(base + (0*GARR + r0s*GPAD + g0s)*2, &Ahg[(size_t)(m0+r0s)*K + kb + g0s]);
        cp_async16(base + (1*GARR + r0s*GPAD + g0s)*2, &Alg[(size_t)(m0+r0s)*K + kb + g0s]);
        cp_async16(base + (2*GARR + r0s*GPAD + g0s)*2, &Bhg[(size_t)(n0+r0s)*K + kb + g0s]);
        cp_async16(base + (3*GARR + r0s*GPAD + g0s)*2, &Blg[(size_t)(n0+r0s)*K + kb + g0s]);
        // chunk 1
        cp_async16(base + (0*GARR + r1s*GPAD + g1s)*2, &Ahg[(size_t)(m0+r1s)*K + kb + g1s]);
        cp_async16(base + (1*GARR + r1s*GPAD + g1s)*2, &Alg[(size_t)(m0+r1s)*K + kb + g1s]);
        cp_async16(base + (2*GARR + r1s*GPAD + g1s)*2, &Bhg[(size_t)(n0+r1s)*K + kb + g1s]);
        cp_async16(base + (3*GARR + r1s*GPAD + g1s)*2, &Blg[(size_t)(n0+r1s)*K + kb + g1s]);
    };

    stage(0, 0);
    CP_COMMIT();

    int s = 0;
    for (int kb = 0; kb < K; kb += 32) {
        if (kb + 32 < K) { stage(s ^ 1, kb + 32); CP_COMMIT(); CP_WAIT_1(); }
        else            { CP_WAIT_0(); }
        __syncthreads();

        const __nv_bfloat16* Ah = sm + s * GSTAGE;
        const __nv_bfloat16* Al = Ah + GARR;
        const __nv_bfloat16* Bh = Al + GARR;
        const __nv_bfloat16* Bl = Bh + GARR;

        #pragma unroll
        for (int kk = 0; kk < 2; kk++) {
            const int kcol = kk * 16 + qt * 2;
            uint32_t aH[4][4], bH[4][2], tA[4][4], tB[4][2];

            #pragma unroll
            for (int mt = 0; mt < 4; mt++) {
                const int r = warpM + mt * 16 + gq;
                aH[mt][0] = *(const uint32_t*)&Ah[r * GPAD + kcol];
                aH[mt][1] = *(const uint32_t*)&Ah[(r + 8) * GPAD + kcol];
                aH[mt][2] = *(const uint32_t*)&Ah[r * GPAD + kcol + 8];
                aH[mt][3] = *(const uint32_t*)&Ah[(r + 8) * GPAD + kcol + 8];
            }
            #pragma unroll
            for (int nt = 0; nt < 4; nt++) {
                const int r = warpN + nt * 8 + gq;
                bH[nt][0] = *(const uint32_t*)&Bh[r * GPAD + kcol];
                bH[nt][1] = *(const uint32_t*)&Bh[r * GPAD + kcol + 8];
            }
            #pragma unroll
            for (int mt = 0; mt < 4; mt++)
                #pragma unroll
                for (int nt = 0; nt < 4; nt++)
                    mma16816(c[mt * 4 + nt], aH[mt], bH[nt]);

            #pragma unroll
            for (int nt = 0; nt < 4; nt++) {
                const int r = warpN + nt * 8 + gq;
                tB[nt][0] = *(const uint32_t*)&Bl[r * GPAD + kcol];
                tB[nt][1] = *(const uint32_t*)&Bl[r * GPAD + kcol + 8];
            }
            #pragma unroll
            for (int mt = 0; mt < 4; mt++)
                #pragma unroll
                for (int nt = 0; nt < 4; nt++)
                    mma16816(c[mt * 4 + nt], aH[mt], tB[nt]);

            #pragma unroll
            for (int mt = 0; mt < 4; mt++) {
                const int r = warpM + mt * 16 + gq;
                tA[mt][0] = *(const uint32_t*)&Al[r * GPAD + kcol];
                tA[mt][1] = *(const uint32_t*)&Al[(r + 8) * GPAD + kcol];
                tA[mt][2] = *(const uint32_t*)&Al[r * GPAD + kcol + 8];
                tA[mt][3] = *(const uint32_t*)&Al[(r + 8) * GPAD + kcol + 8];
            }
            #pragma unroll
            for (int mt = 0; mt < 4; mt++)
                #pragma unroll
                for (int nt = 0; nt < 4; nt++)
                    mma16816(c[mt * 4 + nt], tA[mt], bH[nt]);
        }
        __syncthreads();
        s ^= 1;
    }

    // epilogue
    #pragma unroll
    for (int mt = 0; mt < 4; mt++) {
        const int r0 = m0 + warpM + mt * 16 + gq;
        #pragma unroll
        for (int nt = 0; nt < 4; nt++) {
            const int col = n0 + warpN + nt * 8 + qt * 2;
            const float2 bb = *(const float2*)&bias[col];
            float* cc = c[mt * 4 + nt];
            const float v0 = cc[0] + bb.x, v1 = cc[1] + bb.y;
            const float v2 = cc[2] + bb.x, v3 = cc[3] + bb.y;
            if (Ch) {
                uint32_t h0 = pack_bf16(v0, v1);
                uint32_t h1 = pack_bf16(v2, v3);
                __nv_bfloat162 H0 = *(__nv_bfloat162*)&h0;
                __nv_bfloat162 H1 = *(__nv_bfloat162*)&h1;
                uint32_t l0 = pack_bf16(v0 - __bfloat162float(H0.x),
                                        v1 - __bfloat162float(H0.y));
                uint32_t l1 = pack_bf16(v2 - __bfloat162float(H1.x),
                                        v3 - __bfloat162float(H1.y));
                *(uint32_t*)&Ch[(size_t)r0 * N + col]       = h0;
                *(uint32_t*)&Cl[(size_t)r0 * N + col]       = l0;
                *(uint32_t*)&Ch[(size_t)(r0 + 8) * N + col] = h1;
                *(uint32_t*)&Cl[(size_t)(r0 + 8) * N + col] = l1;
            } else {
                *(float2*)&Cf[(size_t)r0 * N + col]       = make_float2(v0, v1);
                *(float2*)&Cf[(size_t)(r0 + 8) * N + col] = make_float2(v2, v3);
            }
        }
    }
}

// ===========================================================================
// Tensor-core flash attention; pre-split bf16 Q/K/V, cp.async double-buffered
// K/V staging, ldmatrix.trans for V fragments (no explicit transpose).
// CTA: 128 queries x (b,h), 8 warps, key tiles of 64.
// stage = Kh|Kl|Vh|Vl, each 64 rows x 64 bf16 (pad 72). 36864 B, x2 stages.
// ===========================================================================
#define APAD 72
#define AARR (64 * APAD)            // 4608 el
#define ASTAGE (4 * AARR)           // 18432 el = 36864 B
#define ATTN_SMEM (2 * ASTAGE * 2)  // 73728 B dynamic

__global__ __launch_bounds__(256, 1) void attn_tc(
    const __nv_bfloat16* __restrict__ qh, const __nv_bfloat16* __restrict__ ql,
    const float* __restrict__ dd,
    __nv_bfloat16* __restrict__ outh, __nv_bfloat16* __restrict__ outl)
{
    extern __shared__ __nv_bfloat16 sm[];
    __shared__ float dtab[2048];
    const uint32_t smb = smem_u32(sm);

    const int tid = threadIdx.x;
    const int wid = tid >> 5;
    const int lid = tid & 31;
    const int gq  = lid >> 2;
    const int qt  = lid & 3;
    const int q0 = blockIdx.x * 128;
    const int h  = blockIdx.y;
    const int b  = blockIdx.z;

    const float na = fabsf(dd[0]);
    #pragma unroll
    for (int t = tid; t < 2048; t += 256)
        dtab[t] = __expf(-na * (float)t);

    const size_t rowbase = (size_t)b * S_;
    const int colQ = h * D_;
    const int colK = colQ + E_;
    const int colV = colQ + 2 * E_;

    // ---- stage Q (hi 128x64 + lo) into stage-0 region via cp.async ----
    #pragma unroll
    for (int it = 0; it < 8; it++) {
        const int idx = tid + it * 256;       // 0..2047
        const int arr = idx >> 10;            // 0 hi, 1 lo
        const int i   = idx & 1023;
        const int row = i >> 3, seg = (i & 7) * 8;
        const __nv_bfloat16* src = (arr ? ql : qh)
            + (rowbase + q0 + row) * E3_ + colQ + seg;
        cp_async16(smb + (uint32_t)(arr * 2 * AARR + row * APAD + seg) * 2, src);
    }
    CP_COMMIT(); CP_WAIT_0();
    __syncthreads();

    // build Q fragments
    uint32_t aQh[4][4], aQl[4][4];
    {
        const __nv_bfloat16* Qh = sm;
        const __nv_bfloat16* Ql = sm + 2 * AARR;
        const int r0 = wid * 16 + gq;
        #pragma unroll
        for (int kc = 0; kc < 4; kc++) {
            #pragma unroll
            for (int p = 0; p < 4; p++) {
                const int rr = r0 + ((p & 1) ? 8 : 0);
                const int cc = kc * 16 + qt * 2 + ((p & 2) ? 8 : 0);
                aQh[kc][p] = *(const uint32_t*)&Qh[rr * APAD + cc];
                aQl[kc][p] = *(const uint32_t*)&Ql[rr * APAD + cc];
            }
        }
    }
    __syncthreads();   // Q region free for K/V stage 0

    // K/V tile staging (2048 chunks: Kh,Kl,Vh,Vl x 512)
    auto stageKV = [&](int s, int k0) {
        const uint32_t base = smb + (uint32_t)(s * ASTAGE) * 2;
        #pragma unroll
        for (int it = 0; it < 8; it++) {
            const int idx = tid + it * 256;
            const int arr = idx >> 9;              // 0 Kh 1 Kl 2 Vh 3 Vl
            const int i   = idx & 511;
            const int row = i >> 3, seg = (i & 7) * 8;
            const int col = (arr < 2 ? colK : colV) + seg;
            const __nv_bfloat16* src = ((arr & 1) ? ql : qh)
                + (rowbase + k0 + row) * E3_ + col;
            cp_async16(base + (uint32_t)(arr * AARR + row * APAD + seg) * 2, src);
        }
    };

    float m_i[2] = {-INFINITY, -INFINITY};
    float l_i[2] = {0.f, 0.f};
    float O[8][4];
    #pragma unroll
    for (int i = 0; i < 8; i++)
        O[i][0] = O[i][1] = O[i][2] = O[i][3] = 0.f;

    const int qrow0 = q0 + wid * 16 + gq;
    // ldmatrix lane coords for V
    const int t_loc = (lid & 7) + (lid & 8);     // 0..15
    const int d_grp = (lid & 16) >> 1;           // 0 or 8

    stageKV(0, 0);
    CP_COMMIT();

    int s = 0;
    for (int k0 = 0; k0 < S_; k0 += 64) {
        if (k0 + 64 < S_) { stageKV(s ^ 1, k0 + 64); CP_COMMIT(); CP_WAIT_1(); }
        else              { CP_WAIT_0(); }
        __syncthreads();

        const __nv_bfloat16* Kh = sm + s * ASTAGE;
        const __nv_bfloat16* Kl = Kh + AARR;
        const uint32_t vhb = smb + (uint32_t)(s * ASTAGE + 2 * AARR) * 2;
        const uint32_t vlb = vhb + (uint32_t)AARR * 2;

        // ---- S = Q K^T (split, 3 pass) ----
        float S[8][4];
        #pragma unroll
        for (int i = 0; i < 8; i++)
            S[i][0] = S[i][1] = S[i][2] = S[i][3] = 0.f;

        #pragma unroll
        for (int kc = 0; kc < 4; kc++) {
            #pragma unroll
            for (int nt = 0; nt < 8; nt++) {
                const int kr = nt * 8 + gq;
                const int cc = kc * 16 + qt * 2;
                uint32_t bh[2], bl[2];
                bh[0] = *(const uint32_t*)&Kh[kr * APAD + cc];
                bh[1] = *(const uint32_t*)&Kh[kr * APAD + cc + 8];
                bl[0] = *(const uint32_t*)&Kl[kr * APAD + cc];
                bl[1] = *(const uint32_t*)&Kl[kr * APAD + cc + 8];
                mma16816(S[nt], aQh[kc], bh);
                mma16816(S[nt], aQh[kc], bl);
                mma16816(S[nt], aQl[kc], bh);
            }
        }

        // ---- scale * decay, online softmax ----
        float rm0 = -INFINITY, rm1 = -INFINITY;
        #pragma unroll
        for (int nt = 0; nt < 8; nt++) {
            const int kcol = k0 + nt * 8 + qt * 2;
            S[nt][0] *= 0.125f * dtab[abs(qrow0 - kcol)];
            S[nt][1] *= 0.125f * dtab[abs(qrow0 - kcol - 1)];
            S[nt][2] *= 0.125f * dtab[abs(qrow0 + 8 - kcol)];
            S[nt][3] *= 0.125f * dtab[abs(qrow0 + 8 - kcol - 1)];
            rm0 = fmaxf(rm0, fmaxf(S[nt][0], S[nt][1]));
            rm1 = fmaxf(rm1, fmaxf(S[nt][2], S[nt][3]));
        }
        rm0 = fmaxf(rm0, __shfl_xor_sync(0xffffffffu, rm0, 1));
        rm0 = fmaxf(rm0, __shfl_xor_sync(0xffffffffu, rm0, 2));
        rm1 = fmaxf(rm1, __shfl_xor_sync(0xffffffffu, rm1, 1));
        rm1 = fmaxf(rm1, __shfl_xor_sync(0xffffffffu, rm1, 2));

        const float mn0 = fmaxf(m_i[0], rm0);
        const float mn1 = fmaxf(m_i[1], rm1);
        const float sc0 = __expf(m_i[0] - mn0);
        const float sc1 = __expf(m_i[1] - mn1);

        float rs0 = 0.f, rs1 = 0.f;
        #pragma unroll
        for (int nt = 0; nt < 8; nt++) {
            S[nt][0] = __expf(S[nt][0] - mn0);
            S[nt][1] = __expf(S[nt][1] - mn0);
            S[nt][2] = __expf(S[nt][2] - mn1);
            S[nt][3] = __expf(S[nt][3] - mn1);
            rs0 += S[nt][0] + S[nt][1];
            rs1 += S[nt][2] + S[nt][3];
        }
        rs0 += __shfl_xor_sync(0xffffffffu, rs0, 1);
        rs0 += __shfl_xor_sync(0xffffffffu, rs0, 2);
        rs1 += __shfl_xor_sync(0xffffffffu, rs1, 1);
        rs1 += __shfl_xor_sync(0xffffffffu, rs1, 2);

        l_i[0] = l_i[0] * sc0 + rs0;
        l_i[1] = l_i[1] * sc1 + rs1;
        m_i[0] = mn0;
        m_i[1] = mn1;

        #pragma unroll
        for (int i = 0; i < 8; i++) {
            O[i][0] *= sc0; O[i][1] *= sc0;
            O[i][2] *= sc1; O[i][3] *= sc1;
        }

        // ---- pack P fragments (register-only) ----
        uint32_t aPh[4][4], aPl[4][4];
        #pragma unroll
        for (int j = 0; j < 4; j++) {
            const float* s0 = S[2 * j];
            const float* s1 = S[2 * j + 1];
            aPh[j][0] = pack_bf16(s0[0], s0[1]);
            aPh[j][1] = pack_bf16(s0[2], s0[3]);
            aPh[j][2] = pack_bf16(s1[0], s1[1]);
            aPh[j][3] = pack_bf16(s1[2], s1[3]);
            __nv_bfloat162 h0 = *(__nv_bfloat162*)&aPh[j][0];
            __nv_bfloat162 h1 = *(__nv_bfloat162*)&aPh[j][1];
            __nv_bfloat162 h2 = *(__nv_bfloat162*)&aPh[j][2];
            __nv_bfloat162 h3 = *(__nv_bfloat162*)&aPh[j][3];
            aPl[j][0] = pack_bf16(s0[0] - __bfloat162float(h0.x),
                                  s0[1] - __bfloat162float(h0.y));
            aPl[j][1] = pack_bf16(s0[2] - __bfloat162float(h1.x),
                                  s0[3] - __bfloat162float(h1.y));
            aPl[j][2] = pack_bf16(s1[0] - __bfloat162float(h2.x),
                                  s1[1] - __bfloat162float(h2.y));
            aPl[j][3] = pack_bf16(s1[2] - __bfloat162float(h3.x),
                                  s1[3] - __bfloat162float(h3.y));
        }

        // ---- O += P V  via ldmatrix.trans on row-major V ----
        #pragma unroll
        for (int j = 0; j < 4; j++) {
            #pragma unroll
            for (int db = 0; db < 4; db++) {
                const uint32_t off =
                    (uint32_t)((j * 16 + t_loc) * APAD + db * 16 + d_grp) * 2;
                uint32_t vh[4], vl[4];
                ldsm4t(vh, vhb + off);
                ldsm4t(vl, vlb + off);
                mma16816(O[2 * db],     aPh[j], &vh[0]);
                mma16816(O[2 * db],     aPh[j], &vl[0]);
                mma16816(O[2 * db],     aPl[j], &vh[0]);
                mma16816(O[2 * db + 1], aPh[j], &vh[2]);
                mma16816(O[2 * db + 1], aPh[j], &vl[2]);
                mma16816(O[2 * db + 1], aPl[j], &vh[2]);
            }
        }
        __syncthreads();
        s ^= 1;
    }

    // ---- epilogue: split-bf16 output [b,s,h*64+d] ----
    const float inv0 = 1.0f / l_i[0];
    const float inv1 = 1.0f / l_i[1];
    #pragma unroll
    for (int nt = 0; nt < 8; nt++) {
        const int col = h * D_ + nt * 8 + qt * 2;
        const size_t r0 = rowbase + qrow0;
        const float v0 = O[nt][0] * inv0, v1 = O[nt][1] * inv0;
        const float v2 = O[nt][2] * inv1, v3 = O[nt][3] * inv1;
        uint32_t h0 = pack_bf16(v0, v1);
        uint32_t h1 = pack_bf16(v2, v3);
        __nv_bfloat162 H0 = *(__nv_bfloat162*)&h0;
        __nv_bfloat162 H1 = *(__nv_bfloat162*)&h1;
        uint32_t l0 = pack_bf16(v0 - __bfloat162float(H0.x),
                                v1 - __bfloat162float(H0.y));
        uint32_t l1 = pack_bf16(v2 - __bfloat162float(H1.x),
                                v3 - __bfloat162float(H1.y));
        *(uint32_t*)&outh[r0 * E_ + col]       = h0;
        *(uint32_t*)&outl[r0 * E_ + col]       = l0;
        *(uint32_t*)&outh[(r0 + 8) * E_ + col] = h1;
        *(uint32_t*)&outl[(r0 + 8) * E_ + col] = l1;
    }
}

// ===========================================================================
extern "C" void kernel_launch(void* const* d_in, const int* in_sizes, int n_in,
                              void* d_out, int out_size)
{
    const float* x      = (const float*)d_in[0];
    const float* Wqkv_w = (const float*)d_in[1];
    const float* Wqkv_b = (const float*)d_in[2];
    const float* out_w  = (const float*)d_in[3];
    const float* out_b  = (const float*)d_in[4];
    const float* dd     = (const float*)d_in[5];
    float* out = (float*)d_out;

    __nv_bfloat16 *xh, *xl, *wqh, *wql, *owh, *owl, *qkvh, *qkvl, *ath, *atl;
    cudaGetSymbolAddress((void**)&xh,  g_xh);  cudaGetSymbolAddress((void**)&xl,  g_xl);
    cudaGetSymbolAddress((void**)&wqh, g_wqh); cudaGetSymbolAddress((void**)&wql, g_wql);
    cudaGetSymbolAddress((void**)&owh, g_owh); cudaGetSymbolAddress((void**)&owl, g_owl);
    cudaGetSymbolAddress((void**)&qkvh, g_qkvh); cudaGetSymbolAddress((void**)&qkvl, g_qkvl);
    cudaGetSymbolAddress((void**)&ath, g_ath); cudaGetSymbolAddress((void**)&atl, g_atl);

    cudaFuncSetAttribute(gemm_tc, cudaFuncAttributeMaxDynamicSharedMemorySize,
                         GEMM_SMEM);
    cudaFuncSetAttribute(attn_tc, cudaFuncAttributeMaxDynamicSharedMemorySize,
                         ATTN_SMEM);

    // 0. split inputs/weights to bf16 hi/lo
    split_bf16<<<(M_ * E_ / 4 + 255) / 256, 256>>>(x, xh, xl, M_ * E_ / 4);
    split_bf16<<<(E3_ * E_ / 4 + 255) / 256, 256>>>(Wqkv_w, wqh, wql, E3_ * E_ / 4);
    split_bf16<<<(E_ * E_ / 4 + 255) / 256, 256>>>(out_w, owh, owl, E_ * E_ / 4);

    // 1. QKV projection -> split bf16 qkv
    gemm_tc<<<dim3(E3_ / 128, M_ / 128), 256, GEMM_SMEM>>>(
        xh, xl, wqh, wql, Wqkv_b, nullptr, qkvh, qkvl, M_, E3_, E_);

    // 2. attention -> split bf16 attn out
    attn_tc<<<dim3(S_ / 128, H_, B_), 256, ATTN_SMEM>>>(qkvh, qkvl, dd, ath, atl);

    // 3. output projection -> fp32 out
    gemm_tc<<<dim3(E_ / 128, M_ / 128), 256, GEMM_SMEM>>>(
        ath, atl, owh, owl, out_b, out, nullptr, nullptr, M_, E_, E_);
}

// round 10
// speedup vs baseline: 2.8921x; 1.0646x over previous
#include <cuda_runtime.h>
#include <cuda_bf16.h>
#include <math.h>
#include <stdint.h>

#define B_  2
#define S_  2048
#define E_  1024
#define H_  16
#define D_  64
#define E3_ 3072
#define M_  (B_ * S_)   // 4096

// ---------------- device-global scratch (allocation-free rule) -------------
__device__ __nv_bfloat16 g_xh [(size_t)M_  * E_ ], g_xl [(size_t)M_  * E_ ];
__device__ __nv_bfloat16 g_wqh[(size_t)E3_ * E_ ], g_wql[(size_t)E3_ * E_ ];
__device__ __nv_bfloat16 g_owh[(size_t)E_  * E_ ], g_owl[(size_t)E_  * E_ ];
__device__ __nv_bfloat16 g_qkvh[(size_t)M_ * E3_], g_qkvl[(size_t)M_ * E3_];
__device__ __nv_bfloat16 g_ath[(size_t)M_  * E_ ], g_atl[(size_t)M_  * E_ ];

// ---------------- PTX helpers (baseline ISA only) --------------------------
__device__ __forceinline__ void mma16816(float* c, const uint32_t* a,
                                         const uint32_t* b) {
    asm volatile(
        "mma.sync.aligned.m16n8k16.row.col.f32.bf16.bf16.f32 "
        "{%0,%1,%2,%3}, {%4,%5,%6,%7}, {%8,%9}, {%0,%1,%2,%3};"
        : "+f"(c[0]), "+f"(c[1]), "+f"(c[2]), "+f"(c[3])
        : "r"(a[0]), "r"(a[1]), "r"(a[2]), "r"(a[3]), "r"(b[0]), "r"(b[1]));
}

__device__ __forceinline__ uint32_t pack_bf16(float a, float b) {
    __nv_bfloat162 h = __floats2bfloat162_rn(a, b);
    return *(uint32_t*)&h;
}

__device__ __forceinline__ uint32_t smem_u32(const void* p) {
    uint32_t a;
    asm("{ .reg .u64 t; cvta.to.shared.u64 t, %1; cvt.u32.u64 %0, t; }"
        : "=r"(a) : "l"(p));
    return a;
}

__device__ __forceinline__ void cp_async16(uint32_t dst, const void* src) {
    asm volatile("cp.async.ca.shared.global [%0], [%1], 16;"
                 :: "r"(dst), "l"(src));
}
#define CP_COMMIT() asm volatile("cp.async.commit_group;" ::: "memory")
#define CP_WAIT_1() asm volatile("cp.async.wait_group 1;" ::: "memory")
#define CP_WAIT_0() asm volatile("cp.async.wait_group 0;" ::: "memory")

// non-transposed ldmatrix x4 (4 independent 8x8 b16 tiles)
__device__ __forceinline__ void ldsm4(uint32_t* r, uint32_t addr) {
    asm volatile(
        "ldmatrix.sync.aligned.m8n8.x4.shared.b16 {%0,%1,%2,%3}, [%4];"
        : "=r"(r[0]), "=r"(r[1]), "=r"(r[2]), "=r"(r[3]) : "r"(addr));
}
// transposed ldmatrix x4 (for V)
__device__ __forceinline__ void ldsm4t(uint32_t* r, uint32_t addr) {
    asm volatile(
        "ldmatrix.sync.aligned.m8n8.x4.trans.shared.b16 {%0,%1,%2,%3}, [%4];"
        : "=r"(r[0]), "=r"(r[1]), "=r"(r[2]), "=r"(r[3]) : "r"(addr));
}

// ---------------- split fp32 -> bf16 hi/lo ---------------------------------
__global__ __launch_bounds__(256) void split_bf16(
    const float* __restrict__ src, __nv_bfloat16* __restrict__ hi,
    __nv_bfloat16* __restrict__ lo, int n4)
{
    const int i = blockIdx.x * 256 + threadIdx.x;
    if (i >= n4) return;
    float4 v = ((const float4*)src)[i];
    uint32_t h0 = pack_bf16(v.x, v.y);
    uint32_t h1 = pack_bf16(v.z, v.w);
    __nv_bfloat162 H0 = *(__nv_bfloat162*)&h0;
    __nv_bfloat162 H1 = *(__nv_bfloat162*)&h1;
    uint32_t l0 = pack_bf16(v.x - __bfloat162float(H0.x),
                            v.y - __bfloat162float(H0.y));
    uint32_t l1 = pack_bf16(v.z - __bfloat162float(H1.x),
                            v.w - __bfloat162float(H1.y));
    ((uint2*)hi)[i] = make_uint2(h0, h1);
    ((uint2*)lo)[i] = make_uint2(l0, l1);
}

// ===========================================================================
// Split-bf16 HMMA GEMM; pre-split operands, cp.async double-buffer,
// ldmatrix.x4 fragment loads.
// C = A[M,K] * B[N,K]^T + bias.  Output fp32 (Cf) or split bf16 (Ch/Cl).
// ===========================================================================
#define GPAD 40
#define GARR (128 * GPAD)          // 5120 el per array
#define GSTAGE (4 * GARR)          // 20480 el = 40960 B per stage
#define GEMM_SMEM (2 * GSTAGE * 2) // bytes

__global__ __launch_bounds__(256, 2) void gemm_tc(
    const __nv_bfloat16* __restrict__ Ahg, const __nv_bfloat16* __restrict__ Alg,
    const __nv_bfloat16* __restrict__ Bhg, const __nv_bfloat16* __restrict__ Blg,
    const float* __restrict__ bias,
    float* __restrict__ Cf, __nv_bfloat16* __restrict__ Ch,
    __nv_bfloat16* __restrict__ Cl,
    int M, int N, int K)
{
    extern __shared__ __nv_bfloat16 sm[];
    const uint32_t smb = smem_u32(sm);

    const int tid = threadIdx.x;
    const int wid = tid >> 5;
    const int lid = tid & 31;
    const int gq  = lid >> 2;
    const int qt  = lid & 3;
    const int m0 = blockIdx.y * 128;
    const int n0 = blockIdx.x * 128;
    const int warpM = (wid >> 2) * 64;
    const int warpN = (wid & 3) * 32;

    // ldmatrix lane coordinates
    const int a_r = (lid & 7) + ((lid & 8)  ? 8 : 0);  // A-type: row ofs
    const int a_c = (lid & 16) ? 8 : 0;                // A-type: col ofs
    const int b_r = (lid & 7) + ((lid & 16) ? 8 : 0);  // B-type: row ofs
    const int b_c = (lid & 8) ? 8 : 0;                 // B-type: col ofs

    float c[16][4];
    #pragma unroll
    for (int i = 0; i < 16; i++)
        c[i][0] = c[i][1] = c[i][2] = c[i][3] = 0.f;

    const int r0s = (tid + 0)   >> 2, g0s = (tid & 3) * 8;
    const int r1s = (tid + 256) >> 2, g1s = g0s;

    auto stage = [&](int s, int kb) {
        const uint32_t base = smb + (uint32_t)(s * GSTAGE) * 2;
        cp_async16(base + (0*GARR + r0s*GPAD + g0s)*2, &Ahg[(size_t)(m0+r0s)*K + kb + g0s]);
        cp_async16(base + (1*GARR + r0s*GPAD + g0s)*2, &Alg[(size_t)(m0+r0s)*K + kb + g0s]);
        cp_async16(base + (2*GARR + r0s*GPAD + g0s)*2, &Bhg[(size_t)(n0+r0s)*K + kb + g0s]);
        cp_async16(base + (3*GARR + r0s*GPAD + g0s)*2, &Blg[(size_t)(n0+r0s)*K + kb + g0s]);
        cp_async16(base + (0*GARR + r1s*GPAD + g1s)*2, &Ahg[(size_t)(m0+r1s)*K + kb + g1s]);
        cp_async16(base + (1*GARR + r1s*GPAD + g1s)*2, &Alg[(size_t)(m0+r1s)*K + kb + g1s]);
        cp_async16(base + (2*GARR + r1s*GPAD + g1s)*2, &Bhg[(size_t)(n0+r1s)*K + kb + g1s]);
        cp_async16(base + (3*GARR + r1s*GPAD + g1s)*2, &Blg[(size_t)(n0+r1s)*K + kb + g1s]);
    };

    stage(0, 0);
    CP_COMMIT();

    int s = 0;
    for (int kb = 0; kb < K; kb += 32) {
        if (kb + 32 < K) { stage(s ^ 1, kb + 32); CP_COMMIT(); CP_WAIT_1(); }
        else            { CP_WAIT_0(); }
        __syncthreads();

        const uint32_t Ahb = smb + (uint32_t)(s * GSTAGE          ) * 2;
        const uint32_t Alb = smb + (uint32_t)(s * GSTAGE + 1*GARR ) * 2;
        const uint32_t Bhb = smb + (uint32_t)(s * GSTAGE + 2*GARR ) * 2;
        const uint32_t Blb = smb + (uint32_t)(s * GSTAGE + 3*GARR ) * 2;

        #pragma unroll
        for (int kk = 0; kk < 2; kk++) {
            const int kc0 = kk * 16;
            uint32_t aH[4][4], tA[4][4], bH[8], tB[8];

            // hi fragments
            #pragma unroll
            for (int mt = 0; mt < 4; mt++)
                ldsm4(aH[mt], Ahb +
                    (uint32_t)((warpM + mt*16 + a_r) * GPAD + kc0 + a_c) * 2);
            ldsm4(&bH[0], Bhb + (uint32_t)((warpN      + b_r) * GPAD + kc0 + b_c) * 2);
            ldsm4(&bH[4], Bhb + (uint32_t)((warpN + 16 + b_r) * GPAD + kc0 + b_c) * 2);

            // pass 1: Ah * Bh
            #pragma unroll
            for (int mt = 0; mt < 4; mt++)
                #pragma unroll
                for (int nt = 0; nt < 4; nt++)
                    mma16816(c[mt * 4 + nt], aH[mt], &bH[nt * 2]);

            // pass 2: Ah * Bl
            ldsm4(&tB[0], Blb + (uint32_t)((warpN      + b_r) * GPAD + kc0 + b_c) * 2);
            ldsm4(&tB[4], Blb + (uint32_t)((warpN + 16 + b_r) * GPAD + kc0 + b_c) * 2);
            #pragma unroll
            for (int mt = 0; mt < 4; mt++)
                #pragma unroll
                for (int nt = 0; nt < 4; nt++)
                    mma16816(c[mt * 4 + nt], aH[mt], &tB[nt * 2]);

            // pass 3: Al * Bh
            #pragma unroll
            for (int mt = 0; mt < 4; mt++)
                ldsm4(tA[mt], Alb +
                    (uint32_t)((warpM + mt*16 + a_r) * GPAD + kc0 + a_c) * 2);
            #pragma unroll
            for (int mt = 0; mt < 4; mt++)
                #pragma unroll
                for (int nt = 0; nt < 4; nt++)
                    mma16816(c[mt * 4 + nt], tA[mt], &bH[nt * 2]);
        }
        __syncthreads();
        s ^= 1;
    }

    // epilogue
    #pragma unroll
    for (int mt = 0; mt < 4; mt++) {
        const int r0 = m0 + warpM + mt * 16 + gq;
        #pragma unroll
        for (int nt = 0; nt < 4; nt++) {
            const int col = n0 + warpN + nt * 8 + qt * 2;
            const float2 bb = *(const float2*)&bias[col];
            float* cc = c[mt * 4 + nt];
            const float v0 = cc[0] + bb.x, v1 = cc[1] + bb.y;
            const float v2 = cc[2] + bb.x, v3 = cc[3] + bb.y;
            if (Ch) {
                uint32_t h0 = pack_bf16(v0, v1);
                uint32_t h1 = pack_bf16(v2, v3);
                __nv_bfloat162 H0 = *(__nv_bfloat162*)&h0;
                __nv_bfloat162 H1 = *(__nv_bfloat162*)&h1;
                uint32_t l0 = pack_bf16(v0 - __bfloat162float(H0.x),
                                        v1 - __bfloat162float(H0.y));
                uint32_t l1 = pack_bf16(v2 - __bfloat162float(H1.x),
                                        v3 - __bfloat162float(H1.y));
                *(uint32_t*)&Ch[(size_t)r0 * N + col]       = h0;
                *(uint32_t*)&Cl[(size_t)r0 * N + col]       = l0;
                *(uint32_t*)&Ch[(size_t)(r0 + 8) * N + col] = h1;
                *(uint32_t*)&Cl[(size_t)(r0 + 8) * N + col] = l1;
            } else {
                *(float2*)&Cf[(size_t)r0 * N + col]       = make_float2(v0, v1);
                *(float2*)&Cf[(size_t)(r0 + 8) * N + col] = make_float2(v2, v3);
            }
        }
    }
}

// ===========================================================================
// Tensor-core flash attention; pre-split bf16 Q/K/V, cp.async double-buffer,
// ldmatrix.x4 for K fragments, ldmatrix.x4.trans for V.
// ===========================================================================
#define APAD 72
#define AARR (64 * APAD)            // 4608 el
#define ASTAGE (4 * AARR)           // 18432 el = 36864 B
#define ATTN_SMEM (2 * ASTAGE * 2)  // 73728 B dynamic

__global__ __launch_bounds__(256, 1) void attn_tc(
    const __nv_bfloat16* __restrict__ qh, const __nv_bfloat16* __restrict__ ql,
    const float* __restrict__ dd,
    __nv_bfloat16* __restrict__ outh, __nv_bfloat16* __restrict__ outl)
{
    extern __shared__ __nv_bfloat16 sm[];
    __shared__ float dtab[2048];
    const uint32_t smb = smem_u32(sm);

    const int tid = threadIdx.x;
    const int wid = tid >> 5;
    const int lid = tid & 31;
    const int gq  = lid >> 2;
    const int qt  = lid & 3;
    const int q0 = blockIdx.x * 128;
    const int h  = blockIdx.y;
    const int b  = blockIdx.z;

    const float na = fabsf(dd[0]);
    #pragma unroll
    for (int t = tid; t < 2048; t += 256)
        dtab[t] = __expf(-na * (float)t);

    const size_t rowbase = (size_t)b * S_;
    const int colQ = h * D_;
    const int colK = colQ + E_;
    const int colV = colQ + 2 * E_;

    // ldmatrix lane coords
    const int k_r = (lid & 7) + ((lid & 16) ? 8 : 0);   // K B-type
    const int k_c = (lid & 8) ? 8 : 0;
    const int t_loc = (lid & 7) + (lid & 8);            // V trans
    const int d_grp = (lid & 16) >> 1;

    // ---- stage Q (hi+lo) into stage-0 region via cp.async ----
    #pragma unroll
    for (int it = 0; it < 8; it++) {
        const int idx = tid + it * 256;
        const int arr = idx >> 10;
        const int i   = idx & 1023;
        const int row = i >> 3, seg = (i & 7) * 8;
        const __nv_bfloat16* src = (arr ? ql : qh)
            + (rowbase + q0 + row) * E3_ + colQ + seg;
        cp_async16(smb + (uint32_t)(arr * 2 * AARR + row * APAD + seg) * 2, src);
    }
    CP_COMMIT(); CP_WAIT_0();
    __syncthreads();

    // build Q fragments (A-type ldmatrix)
    uint32_t aQh[4][4], aQl[4][4];
    {
        const int a_r = (lid & 7) + ((lid & 8) ? 8 : 0);
        const int a_c = (lid & 16) ? 8 : 0;
        const uint32_t Qhb = smb;
        const uint32_t Qlb = smb + (uint32_t)(2 * AARR) * 2;
        const int rr = wid * 16 + a_r;
        #pragma unroll
        for (int kc = 0; kc < 4; kc++) {
            ldsm4(aQh[kc], Qhb + (uint32_t)(rr * APAD + kc * 16 + a_c) * 2);
            ldsm4(aQl[kc], Qlb + (uint32_t)(rr * APAD + kc * 16 + a_c) * 2);
        }
    }
    __syncthreads();

    auto stageKV = [&](int s, int k0) {
        const uint32_t base = smb + (uint32_t)(s * ASTAGE) * 2;
        #pragma unroll
        for (int it = 0; it < 8; it++) {
            const int idx = tid + it * 256;
            const int arr = idx >> 9;
            const int i   = idx & 511;
            const int row = i >> 3, seg = (i & 7) * 8;
            const int col = (arr < 2 ? colK : colV) + seg;
            const __nv_bfloat16* src = ((arr & 1) ? ql : qh)
                + (rowbase + k0 + row) * E3_ + col;
            cp_async16(base + (uint32_t)(arr * AARR + row * APAD + seg) * 2, src);
        }
    };

    float m_i[2] = {-INFINITY, -INFINITY};
    float l_i[2] = {0.f, 0.f};
    float O[8][4];
    #pragma unroll
    for (int i = 0; i < 8; i++)
        O[i][0] = O[i][1] = O[i][2] = O[i][3] = 0.f;

    const int qrow0 = q0 + wid * 16 + gq;

    stageKV(0, 0);
    CP_COMMIT();

    int s = 0;
    for (int k0 = 0; k0 < S_; k0 += 64) {
        if (k0 + 64 < S_) { stageKV(s ^ 1, k0 + 64); CP_COMMIT(); CP_WAIT_1(); }
        else              { CP_WAIT_0(); }
        __syncthreads();

        const uint32_t Khb = smb + (uint32_t)(s * ASTAGE          ) * 2;
        const uint32_t Klb = smb + (uint32_t)(s * ASTAGE + 1*AARR ) * 2;
        const uint32_t vhb = smb + (uint32_t)(s * ASTAGE + 2*AARR ) * 2;
        const uint32_t vlb = smb + (uint32_t)(s * ASTAGE + 3*AARR ) * 2;

        // ---- S = Q K^T (split, 3 pass; ldmatrix.x4 on K) ----
        float S[8][4];
        #pragma unroll
        for (int i = 0; i < 8; i++)
            S[i][0] = S[i][1] = S[i][2] = S[i][3] = 0.f;

        #pragma unroll
        for (int kc = 0; kc < 4; kc++) {
            #pragma unroll
            for (int p = 0; p < 4; p++) {
                const uint32_t off =
                    (uint32_t)((p * 16 + k_r) * APAD + kc * 16 + k_c) * 2;
                uint32_t kh4[4], kl4[4];
                ldsm4(kh4, Khb + off);
                ldsm4(kl4, Klb + off);
                mma16816(S[2*p],     aQh[kc], &kh4[0]);
                mma16816(S[2*p],     aQh[kc], &kl4[0]);
                mma16816(S[2*p],     aQl[kc], &kh4[0]);
                mma16816(S[2*p + 1], aQh[kc], &kh4[2]);
                mma16816(S[2*p + 1], aQh[kc], &kl4[2]);
                mma16816(S[2*p + 1], aQl[kc], &kh4[2]);
            }
        }

        // ---- scale * decay, online softmax ----
        float rm0 = -INFINITY, rm1 = -INFINITY;
        #pragma unroll
        for (int nt = 0; nt < 8; nt++) {
            const int kcol = k0 + nt * 8 + qt * 2;
            S[nt][0] *= 0.125f * dtab[abs(qrow0 - kcol)];
            S[nt][1] *= 0.125f * dtab[abs(qrow0 - kcol - 1)];
            S[nt][2] *= 0.125f * dtab[abs(qrow0 + 8 - kcol)];
            S[nt][3] *= 0.125f * dtab[abs(qrow0 + 8 - kcol - 1)];
            rm0 = fmaxf(rm0, fmaxf(S[nt][0], S[nt][1]));
            rm1 = fmaxf(rm1, fmaxf(S[nt][2], S[nt][3]));
        }
        rm0 = fmaxf(rm0, __shfl_xor_sync(0xffffffffu, rm0, 1));
        rm0 = fmaxf(rm0, __shfl_xor_sync(0xffffffffu, rm0, 2));
        rm1 = fmaxf(rm1, __shfl_xor_sync(0xffffffffu, rm1, 1));
        rm1 = fmaxf(rm1, __shfl_xor_sync(0xffffffffu, rm1, 2));

        const float mn0 = fmaxf(m_i[0], rm0);
        const float mn1 = fmaxf(m_i[1], rm1);
        const float sc0 = __expf(m_i[0] - mn0);
        const float sc1 = __expf(m_i[1] - mn1);

        float rs0 = 0.f, rs1 = 0.f;
        #pragma unroll
        for (int nt = 0; nt < 8; nt++) {
            S[nt][0] = __expf(S[nt][0] - mn0);
            S[nt][1] = __expf(S[nt][1] - mn0);
            S[nt][2] = __expf(S[nt][2] - mn1);
            S[nt][3] = __expf(S[nt][3] - mn1);
            rs0 += S[nt][0] + S[nt][1];
            rs1 += S[nt][2] + S[nt][3];
        }
        rs0 += __shfl_xor_sync(0xffffffffu, rs0, 1);
        rs0 += __shfl_xor_sync(0xffffffffu, rs0, 2);
        rs1 += __shfl_xor_sync(0xffffffffu, rs1, 1);
        rs1 += __shfl_xor_sync(0xffffffffu, rs1, 2);

        l_i[0] = l_i[0] * sc0 + rs0;
        l_i[1] = l_i[1] * sc1 + rs1;
        m_i[0] = mn0;
        m_i[1] = mn1;

        #pragma unroll
        for (int i = 0; i < 8; i++) {
            O[i][0] *= sc0; O[i][1] *= sc0;
            O[i][2] *= sc1; O[i][3] *= sc1;
        }

        // ---- pack P fragments (register-only) ----
        uint32_t aPh[4][4], aPl[4][4];
        #pragma unroll
        for (int j = 0; j < 4; j++) {
            const float* s0 = S[2 * j];
            const float* s1 = S[2 * j + 1];
            aPh[j][0] = pack_bf16(s0[0], s0[1]);
            aPh[j][1] = pack_bf16(s0[2], s0[3]);
            aPh[j][2] = pack_bf16(s1[0], s1[1]);
            aPh[j][3] = pack_bf16(s1[2], s1[3]);
            __nv_bfloat162 h0 = *(__nv_bfloat162*)&aPh[j][0];
            __nv_bfloat162 h1 = *(__nv_bfloat162*)&aPh[j][1];
            __nv_bfloat162 h2 = *(__nv_bfloat162*)&aPh[j][2];
            __nv_bfloat162 h3 = *(__nv_bfloat162*)&aPh[j][3];
            aPl[j][0] = pack_bf16(s0[0] - __bfloat162float(h0.x),
                                  s0[1] - __bfloat162float(h0.y));
            aPl[j][1] = pack_bf16(s0[2] - __bfloat162float(h1.x),
                                  s0[3] - __bfloat162float(h1.y));
            aPl[j][2] = pack_bf16(s1[0] - __bfloat162float(h2.x),
                                  s1[1] - __bfloat162float(h2.y));
            aPl[j][3] = pack_bf16(s1[2] - __bfloat162float(h3.x),
                                  s1[3] - __bfloat162float(h3.y));
        }

        // ---- O += P V  via ldmatrix.trans on row-major V ----
        #pragma unroll
        for (int j = 0; j < 4; j++) {
            #pragma unroll
            for (int db = 0; db < 4; db++) {
                const uint32_t off =
                    (uint32_t)((j * 16 + t_loc) * APAD + db * 16 + d_grp) * 2;
                uint32_t vh[4], vl[4];
                ldsm4t(vh, vhb + off);
                ldsm4t(vl, vlb + off);
                mma16816(O[2 * db],     aPh[j], &vh[0]);
                mma16816(O[2 * db],     aPh[j], &vl[0]);
                mma16816(O[2 * db],     aPl[j], &vh[0]);
                mma16816(O[2 * db + 1], aPh[j], &vh[2]);
                mma16816(O[2 * db + 1], aPh[j], &vl[2]);
                mma16816(O[2 * db + 1], aPl[j], &vh[2]);
            }
        }
        __syncthreads();
        s ^= 1;
    }

    // ---- epilogue: split-bf16 output ----
    const float inv0 = 1.0f / l_i[0];
    const float inv1 = 1.0f / l_i[1];
    #pragma unroll
    for (int nt = 0; nt < 8; nt++) {
        const int col = h * D_ + nt * 8 + qt * 2;
        const size_t r0 = rowbase + qrow0;
        const float v0 = O[nt][0] * inv0, v1 = O[nt][1] * inv0;
        const float v2 = O[nt][2] * inv1, v3 = O[nt][3] * inv1;
        uint32_t h0 = pack_bf16(v0, v1);
        uint32_t h1 = pack_bf16(v2, v3);
        __nv_bfloat162 H0 = *(__nv_bfloat162*)&h0;
        __nv_bfloat162 H1 = *(__nv_bfloat162*)&h1;
        uint32_t l0 = pack_bf16(v0 - __bfloat162float(H0.x),
                                v1 - __bfloat162float(H0.y));
        uint32_t l1 = pack_bf16(v2 - __bfloat162float(H1.x),
                                v3 - __bfloat162float(H1.y));
        *(uint32_t*)&outh[r0 * E_ + col]       = h0;
        *(uint32_t*)&outl[r0 * E_ + col]       = l0;
        *(uint32_t*)&outh[(r0 + 8) * E_ + col] = h1;
        *(uint32_t*)&outl[(r0 + 8) * E_ + col] = l1;
    }
}

// ===========================================================================
extern "C" void kernel_launch(void* const* d_in, const int* in_sizes, int n_in,
                              void* d_out, int out_size)
{
    const float* x      = (const float*)d_in[0];
    const float* Wqkv_w = (const float*)d_in[1];
    const float* Wqkv_b = (const float*)d_in[2];
    const float* out_w  = (const float*)d_in[3];
    const float* out_b  = (const float*)d_in[4];
    const float* dd     = (const float*)d_in[5];
    float* out = (float*)d_out;

    __nv_bfloat16 *xh, *xl, *wqh, *wql, *owh, *owl, *qkvh, *qkvl, *ath, *atl;
    cudaGetSymbolAddress((void**)&xh,  g_xh);  cudaGetSymbolAddress((void**)&xl,  g_xl);
    cudaGetSymbolAddress((void**)&wqh, g_wqh); cudaGetSymbolAddress((void**)&wql, g_wql);
    cudaGetSymbolAddress((void**)&owh, g_owh); cudaGetSymbolAddress((void**)&owl, g_owl);
    cudaGetSymbolAddress((void**)&qkvh, g_qkvh); cudaGetSymbolAddress((void**)&qkvl, g_qkvl);
    cudaGetSymbolAddress((void**)&ath, g_ath); cudaGetSymbolAddress((void**)&atl, g_atl);

    cudaFuncSetAttribute(gemm_tc, cudaFuncAttributeMaxDynamicSharedMemorySize,
                         GEMM_SMEM);
    cudaFuncSetAttribute(attn_tc, cudaFuncAttributeMaxDynamicSharedMemorySize,
                         ATTN_SMEM);

    // 0. split inputs/weights to bf16 hi/lo
    split_bf16<<<(M_ * E_ / 4 + 255) / 256, 256>>>(x, xh, xl, M_ * E_ / 4);
    split_bf16<<<(E3_ * E_ / 4 + 255) / 256, 256>>>(Wqkv_w, wqh, wql, E3_ * E_ / 4);
    split_bf16<<<(E_ * E_ / 4 + 255) / 256, 256>>>(out_w, owh, owl, E_ * E_ / 4);

    // 1. QKV projection -> split bf16 qkv
    gemm_tc<<<dim3(E3_ / 128, M_ / 128), 256, GEMM_SMEM>>>(
        xh, xl, wqh, wql, Wqkv_b, nullptr, qkvh, qkvl, M_, E3_, E_);

    // 2. attention -> split bf16 attn out
    attn_tc<<<dim3(S_ / 128, H_, B_), 256, ATTN_SMEM>>>(qkvh, qkvl, dd, ath, atl);

    // 3. output projection -> fp32 out
    gemm_tc<<<dim3(E_ / 128, M_ / 128), 256, GEMM_SMEM>>>(
        ath, atl, owh, owl, out_b, out, nullptr, nullptr, M_, E_, E_);
}

// round 11
// speedup vs baseline: 3.0919x; 1.0691x over previous
#include <cuda_runtime.h>
#include <cuda_bf16.h>
#include <math.h>
#include <stdint.h>

#define B_  2
#define S_  2048
#define E_  1024
#define H_  16
#define D_  64
#define E3_ 3072
#define M_  (B_ * S_)   // 4096

// ---------------- device-global scratch (allocation-free rule) -------------
__device__ __nv_bfloat16 g_xh [(size_t)M_  * E_ ], g_xl [(size_t)M_  * E_ ];
__device__ __nv_bfloat16 g_wqh[(size_t)E3_ * E_ ], g_wql[(size_t)E3_ * E_ ];
__device__ __nv_bfloat16 g_owh[(size_t)E_  * E_ ], g_owl[(size_t)E_  * E_ ];
__device__ __nv_bfloat16 g_qkvh[(size_t)M_ * E3_], g_qkvl[(size_t)M_ * E3_];
__device__ __nv_bfloat16 g_ath[(size_t)M_  * E_ ], g_atl[(size_t)M_  * E_ ];

// ---------------- PTX helpers (baseline ISA only) --------------------------
__device__ __forceinline__ void mma16816(float* c, const uint32_t* a,
                                         const uint32_t* b) {
    asm volatile(
        "mma.sync.aligned.m16n8k16.row.col.f32.bf16.bf16.f32 "
        "{%0,%1,%2,%3}, {%4,%5,%6,%7}, {%8,%9}, {%0,%1,%2,%3};"
        : "+f"(c[0]), "+f"(c[1]), "+f"(c[2]), "+f"(c[3])
        : "r"(a[0]), "r"(a[1]), "r"(a[2]), "r"(a[3]), "r"(b[0]), "r"(b[1]));
}

__device__ __forceinline__ uint32_t pack_bf16(float a, float b) {
    __nv_bfloat162 h = __floats2bfloat162_rn(a, b);
    return *(uint32_t*)&h;
}

__device__ __forceinline__ uint32_t smem_u32(const void* p) {
    uint32_t a;
    asm("{ .reg .u64 t; cvta.to.shared.u64 t, %1; cvt.u32.u64 %0, t; }"
        : "=r"(a) : "l"(p));
    return a;
}

__device__ __forceinline__ void cp_async16(uint32_t dst, const void* src) {
    asm volatile("cp.async.ca.shared.global [%0], [%1], 16;"
                 :: "r"(dst), "l"(src));
}
#define CP_COMMIT() asm volatile("cp.async.commit_group;" ::: "memory")
#define CP_WAIT_1() asm volatile("cp.async.wait_group 1;" ::: "memory")
#define CP_WAIT_0() asm volatile("cp.async.wait_group 0;" ::: "memory")

__device__ __forceinline__ void ldsm4(uint32_t* r, uint32_t addr) {
    asm volatile(
        "ldmatrix.sync.aligned.m8n8.x4.shared.b16 {%0,%1,%2,%3}, [%4];"
        : "=r"(r[0]), "=r"(r[1]), "=r"(r[2]), "=r"(r[3]) : "r"(addr));
}
__device__ __forceinline__ void ldsm4t(uint32_t* r, uint32_t addr) {
    asm volatile(
        "ldmatrix.sync.aligned.m8n8.x4.trans.shared.b16 {%0,%1,%2,%3}, [%4];"
        : "=r"(r[0]), "=r"(r[1]), "=r"(r[2]), "=r"(r[3]) : "r"(addr));
}

// ---------------- split fp32 -> bf16 hi/lo ---------------------------------
__global__ __launch_bounds__(256) void split_bf16(
    const float* __restrict__ src, __nv_bfloat16* __restrict__ hi,
    __nv_bfloat16* __restrict__ lo, int n4)
{
    const int i = blockIdx.x * 256 + threadIdx.x;
    if (i >= n4) return;
    float4 v = ((const float4*)src)[i];
    uint32_t h0 = pack_bf16(v.x, v.y);
    uint32_t h1 = pack_bf16(v.z, v.w);
    __nv_bfloat162 H0 = *(__nv_bfloat162*)&h0;
    __nv_bfloat162 H1 = *(__nv_bfloat162*)&h1;
    uint32_t l0 = pack_bf16(v.x - __bfloat162float(H0.x),
                            v.y - __bfloat162float(H0.y));
    uint32_t l1 = pack_bf16(v.z - __bfloat162float(H1.x),
                            v.w - __bfloat162float(H1.y));
    ((uint2*)hi)[i] = make_uint2(h0, h1);
    ((uint2*)lo)[i] = make_uint2(l0, l1);
}

// ===========================================================================
// Split-bf16 HMMA GEMM; 4 warps (2x2), 64x64 warp tiles, 2 CTA/SM.
// cp.async double-buffer, ldmatrix.x4 fragment loads.
// C = A[M,K] * B[N,K]^T + bias.  Output fp32 (Cf) or split bf16 (Ch/Cl).
// ===========================================================================
#define GPAD 40
#define GARR (128 * GPAD)          // 5120 el per array
#define GSTAGE (4 * GARR)          // 20480 el = 40960 B per stage
#define GEMM_SMEM (2 * GSTAGE * 2) // 81920 bytes

__global__ __launch_bounds__(128, 2) void gemm_tc(
    const __nv_bfloat16* __restrict__ Ahg, const __nv_bfloat16* __restrict__ Alg,
    const __nv_bfloat16* __restrict__ Bhg, const __nv_bfloat16* __restrict__ Blg,
    const float* __restrict__ bias,
    float* __restrict__ Cf, __nv_bfloat16* __restrict__ Ch,
    __nv_bfloat16* __restrict__ Cl,
    int M, int N, int K)
{
    extern __shared__ __nv_bfloat16 sm[];
    const uint32_t smb = smem_u32(sm);

    const int tid = threadIdx.x;
    const int wid = tid >> 5;
    const int lid = tid & 31;
    const int gq  = lid >> 2;
    const int qt  = lid & 3;
    const int m0 = blockIdx.y * 128;
    const int n0 = blockIdx.x * 128;
    const int warpM = (wid >> 1) * 64;   // 0 or 64
    const int warpN = (wid & 1) * 64;    // 0 or 64

    // ldmatrix lane coordinates
    const int a_r = (lid & 7) + ((lid & 8)  ? 8 : 0);
    const int a_c = (lid & 16) ? 8 : 0;
    const int b_r = (lid & 7) + ((lid & 16) ? 8 : 0);
    const int b_c = (lid & 8) ? 8 : 0;

    float c[4][8][4];                    // [mt][nt][reg] = 128 accum regs
    #pragma unroll
    for (int mt = 0; mt < 4; mt++)
        #pragma unroll
        for (int nt = 0; nt < 8; nt++)
            c[mt][nt][0] = c[mt][nt][1] = c[mt][nt][2] = c[mt][nt][3] = 0.f;

    // staging: 512 16B-chunks per array, 4 per thread per array (128 threads)
    int srow[4], sseg[4];
    #pragma unroll
    for (int i = 0; i < 4; i++) {
        const int idx = tid + i * 128;     // 0..511
        srow[i] = idx >> 2;
        sseg[i] = (idx & 3) * 8;
    }

    auto stage = [&](int s, int kb) {
        const uint32_t base = smb + (uint32_t)(s * GSTAGE) * 2;
        #pragma unroll
        for (int i = 0; i < 4; i++) {
            const int r = srow[i], g = sseg[i];
            cp_async16(base + (uint32_t)(0*GARR + r*GPAD + g)*2,
                       &Ahg[(size_t)(m0 + r) * K + kb + g]);
            cp_async16(base + (uint32_t)(1*GARR + r*GPAD + g)*2,
                       &Alg[(size_t)(m0 + r) * K + kb + g]);
            cp_async16(base + (uint32_t)(2*GARR + r*GPAD + g)*2,
                       &Bhg[(size_t)(n0 + r) * K + kb + g]);
            cp_async16(base + (uint32_t)(3*GARR + r*GPAD + g)*2,
                       &Blg[(size_t)(n0 + r) * K + kb + g]);
        }
    };

    stage(0, 0);
    CP_COMMIT();

    int s = 0;
    for (int kb = 0; kb < K; kb += 32) {
        if (kb + 32 < K) { stage(s ^ 1, kb + 32); CP_COMMIT(); CP_WAIT_1(); }
        else            { CP_WAIT_0(); }
        __syncthreads();

        const uint32_t Ahb = smb + (uint32_t)(s * GSTAGE          ) * 2;
        const uint32_t Alb = smb + (uint32_t)(s * GSTAGE + 1*GARR ) * 2;
        const uint32_t Bhb = smb + (uint32_t)(s * GSTAGE + 2*GARR ) * 2;
        const uint32_t Blb = smb + (uint32_t)(s * GSTAGE + 3*GARR ) * 2;

        #pragma unroll
        for (int kk = 0; kk < 2; kk++) {
            const int kc0 = kk * 16;
            uint32_t aH[4][4], tA[4][4], bH[16], tB[16];

            // hi fragments: 4 A-ldsm + 4 B-ldsm
            #pragma unroll
            for (int mt = 0; mt < 4; mt++)
                ldsm4(aH[mt], Ahb +
                    (uint32_t)((warpM + mt*16 + a_r) * GPAD + kc0 + a_c) * 2);
            #pragma unroll
            for (int p = 0; p < 4; p++)
                ldsm4(&bH[p*4], Bhb +
                    (uint32_t)((warpN + p*16 + b_r) * GPAD + kc0 + b_c) * 2);

            // pass 1: Ah * Bh
            #pragma unroll
            for (int mt = 0; mt < 4; mt++)
                #pragma unroll
                for (int nt = 0; nt < 8; nt++)
                    mma16816(c[mt][nt], aH[mt], &bH[nt * 2]);

            // pass 2: Ah * Bl
            #pragma unroll
            for (int p = 0; p < 4; p++)
                ldsm4(&tB[p*4], Blb +
                    (uint32_t)((warpN + p*16 + b_r) * GPAD + kc0 + b_c) * 2);
            #pragma unroll
            for (int mt = 0; mt < 4; mt++)
                #pragma unroll
                for (int nt = 0; nt < 8; nt++)
                    mma16816(c[mt][nt], aH[mt], &tB[nt * 2]);

            // pass 3: Al * Bh
            #pragma unroll
            for (int mt = 0; mt < 4; mt++)
                ldsm4(tA[mt], Alb +
                    (uint32_t)((warpM + mt*16 + a_r) * GPAD + kc0 + a_c) * 2);
            #pragma unroll
            for (int mt = 0; mt < 4; mt++)
                #pragma unroll
                for (int nt = 0; nt < 8; nt++)
                    mma16816(c[mt][nt], tA[mt], &bH[nt * 2]);
        }
        __syncthreads();
        s ^= 1;
    }

    // epilogue
    #pragma unroll
    for (int mt = 0; mt < 4; mt++) {
        const int r0 = m0 + warpM + mt * 16 + gq;
        #pragma unroll
        for (int nt = 0; nt < 8; nt++) {
            const int col = n0 + warpN + nt * 8 + qt * 2;
            const float2 bb = *(const float2*)&bias[col];
            float* cc = c[mt][nt];
            const float v0 = cc[0] + bb.x, v1 = cc[1] + bb.y;
            const float v2 = cc[2] + bb.x, v3 = cc[3] + bb.y;
            if (Ch) {
                uint32_t h0 = pack_bf16(v0, v1);
                uint32_t h1 = pack_bf16(v2, v3);
                __nv_bfloat162 H0 = *(__nv_bfloat162*)&h0;
                __nv_bfloat162 H1 = *(__nv_bfloat162*)&h1;
                uint32_t l0 = pack_bf16(v0 - __bfloat162float(H0.x),
                                        v1 - __bfloat162float(H0.y));
                uint32_t l1 = pack_bf16(v2 - __bfloat162float(H1.x),
                                        v3 - __bfloat162float(H1.y));
                *(uint32_t*)&Ch[(size_t)r0 * N + col]       = h0;
                *(uint32_t*)&Cl[(size_t)r0 * N + col]       = l0;
                *(uint32_t*)&Ch[(size_t)(r0 + 8) * N + col] = h1;
                *(uint32_t*)&Cl[(size_t)(r0 + 8) * N + col] = l1;
            } else {
                *(float2*)&Cf[(size_t)r0 * N + col]       = make_float2(v0, v1);
                *(float2*)&Cf[(size_t)(r0 + 8) * N + col] = make_float2(v2, v3);
            }
        }
    }
}

// ===========================================================================
// Tensor-core flash attention (unchanged from R10).
// ===========================================================================
#define APAD 72
#define AARR (64 * APAD)            // 4608 el
#define ASTAGE (4 * AARR)           // 18432 el = 36864 B
#define ATTN_SMEM (2 * ASTAGE * 2)  // 73728 B dynamic

__global__ __launch_bounds__(256, 1) void attn_tc(
    const __nv_bfloat16* __restrict__ qh, const __nv_bfloat16* __restrict__ ql,
    const float* __restrict__ dd,
    __nv_bfloat16* __restrict__ outh, __nv_bfloat16* __restrict__ outl)
{
    extern __shared__ __nv_bfloat16 sm[];
    __shared__ float dtab[2048];
    const uint32_t smb = smem_u32(sm);

    const int tid = threadIdx.x;
    const int wid = tid >> 5;
    const int lid = tid & 31;
    const int gq  = lid >> 2;
    const int qt  = lid & 3;
    const int q0 = blockIdx.x * 128;
    const int h  = blockIdx.y;
    const int b  = blockIdx.z;

    const float na = fabsf(dd[0]);
    #pragma unroll
    for (int t = tid; t < 2048; t += 256)
        dtab[t] = __expf(-na * (float)t);

    const size_t rowbase = (size_t)b * S_;
    const int colQ = h * D_;
    const int colK = colQ + E_;
    const int colV = colQ + 2 * E_;

    const int k_r = (lid & 7) + ((lid & 16) ? 8 : 0);
    const int k_c = (lid & 8) ? 8 : 0;
    const int t_loc = (lid & 7) + (lid & 8);
    const int d_grp = (lid & 16) >> 1;

    // ---- stage Q (hi+lo) into stage-0 region via cp.async ----
    #pragma unroll
    for (int it = 0; it < 8; it++) {
        const int idx = tid + it * 256;
        const int arr = idx >> 10;
        const int i   = idx & 1023;
        const int row = i >> 3, seg = (i & 7) * 8;
        const __nv_bfloat16* src = (arr ? ql : qh)
            + (rowbase + q0 + row) * E3_ + colQ + seg;
        cp_async16(smb + (uint32_t)(arr * 2 * AARR + row * APAD + seg) * 2, src);
    }
    CP_COMMIT(); CP_WAIT_0();
    __syncthreads();

    uint32_t aQh[4][4], aQl[4][4];
    {
        const int a_r = (lid & 7) + ((lid & 8) ? 8 : 0);
        const int a_c = (lid & 16) ? 8 : 0;
        const uint32_t Qhb = smb;
        const uint32_t Qlb = smb + (uint32_t)(2 * AARR) * 2;
        const int rr = wid * 16 + a_r;
        #pragma unroll
        for (int kc = 0; kc < 4; kc++) {
            ldsm4(aQh[kc], Qhb + (uint32_t)(rr * APAD + kc * 16 + a_c) * 2);
            ldsm4(aQl[kc], Qlb + (uint32_t)(rr * APAD + kc * 16 + a_c) * 2);
        }
    }
    __syncthreads();

    auto stageKV = [&](int s, int k0) {
        const uint32_t base = smb + (uint32_t)(s * ASTAGE) * 2;
        #pragma unroll
        for (int it = 0; it < 8; it++) {
            const int idx = tid + it * 256;
            const int arr = idx >> 9;
            const int i   = idx & 511;
            const int row = i >> 3, seg = (i & 7) * 8;
            const int col = (arr < 2 ? colK : colV) + seg;
            const __nv_bfloat16* src = ((arr & 1) ? ql : qh)
                + (rowbase + k0 + row) * E3_ + col;
            cp_async16(base + (uint32_t)(arr * AARR + row * APAD + seg) * 2, src);
        }
    };

    float m_i[2] = {-INFINITY, -INFINITY};
    float l_i[2] = {0.f, 0.f};
    float O[8][4];
    #pragma unroll
    for (int i = 0; i < 8; i++)
        O[i][0] = O[i][1] = O[i][2] = O[i][3] = 0.f;

    const int qrow0 = q0 + wid * 16 + gq;

    stageKV(0, 0);
    CP_COMMIT();

    int s = 0;
    for (int k0 = 0; k0 < S_; k0 += 64) {
        if (k0 + 64 < S_) { stageKV(s ^ 1, k0 + 64); CP_COMMIT(); CP_WAIT_1(); }
        else              { CP_WAIT_0(); }
        __syncthreads();

        const uint32_t Khb = smb + (uint32_t)(s * ASTAGE          ) * 2;
        const uint32_t Klb = smb + (uint32_t)(s * ASTAGE + 1*AARR ) * 2;
        const uint32_t vhb = smb + (uint32_t)(s * ASTAGE + 2*AARR ) * 2;
        const uint32_t vlb = smb + (uint32_t)(s * ASTAGE + 3*AARR ) * 2;

        float S[8][4];
        #pragma unroll
        for (int i = 0; i < 8; i++)
            S[i][0] = S[i][1] = S[i][2] = S[i][3] = 0.f;

        #pragma unroll
        for (int kc = 0; kc < 4; kc++) {
            #pragma unroll
            for (int p = 0; p < 4; p++) {
                const uint32_t off =
                    (uint32_t)((p * 16 + k_r) * APAD + kc * 16 + k_c) * 2;
                uint32_t kh4[4], kl4[4];
                ldsm4(kh4, Khb + off);
                ldsm4(kl4, Klb + off);
                mma16816(S[2*p],     aQh[kc], &kh4[0]);
                mma16816(S[2*p],     aQh[kc], &kl4[0]);
                mma16816(S[2*p],     aQl[kc], &kh4[0]);
                mma16816(S[2*p + 1], aQh[kc], &kh4[2]);
                mma16816(S[2*p + 1], aQh[kc], &kl4[2]);
                mma16816(S[2*p + 1], aQl[kc], &kh4[2]);
            }
        }

        float rm0 = -INFINITY, rm1 = -INFINITY;
        #pragma unroll
        for (int nt = 0; nt < 8; nt++) {
            const int kcol = k0 + nt * 8 + qt * 2;
            S[nt][0] *= 0.125f * dtab[abs(qrow0 - kcol)];
            S[nt][1] *= 0.125f * dtab[abs(qrow0 - kcol - 1)];
            S[nt][2] *= 0.125f * dtab[abs(qrow0 + 8 - kcol)];
            S[nt][3] *= 0.125f * dtab[abs(qrow0 + 8 - kcol - 1)];
            rm0 = fmaxf(rm0, fmaxf(S[nt][0], S[nt][1]));
            rm1 = fmaxf(rm1, fmaxf(S[nt][2], S[nt][3]));
        }
        rm0 = fmaxf(rm0, __shfl_xor_sync(0xffffffffu, rm0, 1));
        rm0 = fmaxf(rm0, __shfl_xor_sync(0xffffffffu, rm0, 2));
        rm1 = fmaxf(rm1, __shfl_xor_sync(0xffffffffu, rm1, 1));
        rm1 = fmaxf(rm1, __shfl_xor_sync(0xffffffffu, rm1, 2));

        const float mn0 = fmaxf(m_i[0], rm0);
        const float mn1 = fmaxf(m_i[1], rm1);
        const float sc0 = __expf(m_i[0] - mn0);
        const float sc1 = __expf(m_i[1] - mn1);

        float rs0 = 0.f, rs1 = 0.f;
        #pragma unroll
        for (int nt = 0; nt < 8; nt++) {
            S[nt][0] = __expf(S[nt][0] - mn0);
            S[nt][1] = __expf(S[nt][1] - mn0);
            S[nt][2] = __expf(S[nt][2] - mn1);
            S[nt][3] = __expf(S[nt][3] - mn1);
            rs0 += S[nt][0] + S[nt][1];
            rs1 += S[nt][2] + S[nt][3];
        }
        rs0 += __shfl_xor_sync(0xffffffffu, rs0, 1);
        rs0 += __shfl_xor_sync(0xffffffffu, rs0, 2);
        rs1 += __shfl_xor_sync(0xffffffffu, rs1, 1);
        rs1 += __shfl_xor_sync(0xffffffffu, rs1, 2);

        l_i[0] = l_i[0] * sc0 + rs0;
        l_i[1] = l_i[1] * sc1 + rs1;
        m_i[0] = mn0;
        m_i[1] = mn1;

        #pragma unroll
        for (int i = 0; i < 8; i++) {
            O[i][0] *= sc0; O[i][1] *= sc0;
            O[i][2] *= sc1; O[i][3] *= sc1;
        }

        uint32_t aPh[4][4], aPl[4][4];
        #pragma unroll
        for (int j = 0; j < 4; j++) {
            const float* s0 = S[2 * j];
            const float* s1 = S[2 * j + 1];
            aPh[j][0] = pack_bf16(s0[0], s0[1]);
            aPh[j][1] = pack_bf16(s0[2], s0[3]);
            aPh[j][2] = pack_bf16(s1[0], s1[1]);
            aPh[j][3] = pack_bf16(s1[2], s1[3]);
            __nv_bfloat162 h0 = *(__nv_bfloat162*)&aPh[j][0];
            __nv_bfloat162 h1 = *(__nv_bfloat162*)&aPh[j][1];
            __nv_bfloat162 h2 = *(__nv_bfloat162*)&aPh[j][2];
            __nv_bfloat162 h3 = *(__nv_bfloat162*)&aPh[j][3];
            aPl[j][0] = pack_bf16(s0[0] - __bfloat162float(h0.x),
                                  s0[1] - __bfloat162float(h0.y));
            aPl[j][1] = pack_bf16(s0[2] - __bfloat162float(h1.x),
                                  s0[3] - __bfloat162float(h1.y));
            aPl[j][2] = pack_bf16(s1[0] - __bfloat162float(h2.x),
                                  s1[1] - __bfloat162float(h2.y));
            aPl[j][3] = pack_bf16(s1[2] - __bfloat162float(h3.x),
                                  s1[3] - __bfloat162float(h3.y));
        }

        #pragma unroll
        for (int j = 0; j < 4; j++) {
            #pragma unroll
            for (int db = 0; db < 4; db++) {
                const uint32_t off =
                    (uint32_t)((j * 16 + t_loc) * APAD + db * 16 + d_grp) * 2;
                uint32_t vh[4], vl[4];
                ldsm4t(vh, vhb + off);
                ldsm4t(vl, vlb + off);
                mma16816(O[2 * db],     aPh[j], &vh[0]);
                mma16816(O[2 * db],     aPh[j], &vl[0]);
                mma16816(O[2 * db],     aPl[j], &vh[0]);
                mma16816(O[2 * db + 1], aPh[j], &vh[2]);
                mma16816(O[2 * db + 1], aPh[j], &vl[2]);
                mma16816(O[2 * db + 1], aPl[j], &vh[2]);
            }
        }
        __syncthreads();
        s ^= 1;
    }

    const float inv0 = 1.0f / l_i[0];
    const float inv1 = 1.0f / l_i[1];
    #pragma unroll
    for (int nt = 0; nt < 8; nt++) {
        const int col = h * D_ + nt * 8 + qt * 2;
        const size_t r0 = rowbase + qrow0;
        const float v0 = O[nt][0] * inv0, v1 = O[nt][1] * inv0;
        const float v2 = O[nt][2] * inv1, v3 = O[nt][3] * inv1;
        uint32_t h0 = pack_bf16(v0, v1);
        uint32_t h1 = pack_bf16(v2, v3);
        __nv_bfloat162 H0 = *(__nv_bfloat162*)&h0;
        __nv_bfloat162 H1 = *(__nv_bfloat162*)&h1;
        uint32_t l0 = pack_bf16(v0 - __bfloat162float(H0.x),
                                v1 - __bfloat162float(H0.y));
        uint32_t l1 = pack_bf16(v2 - __bfloat162float(H1.x),
                                v3 - __bfloat162float(H1.y));
        *(uint32_t*)&outh[r0 * E_ + col]       = h0;
        *(uint32_t*)&outl[r0 * E_ + col]       = l0;
        *(uint32_t*)&outh[(r0 + 8) * E_ + col] = h1;
        *(uint32_t*)&outl[(r0 + 8) * E_ + col] = l1;
    }
}

// ===========================================================================
extern "C" void kernel_launch(void* const* d_in, const int* in_sizes, int n_in,
                              void* d_out, int out_size)
{
    const float* x      = (const float*)d_in[0];
    const float* Wqkv_w = (const float*)d_in[1];
    const float* Wqkv_b = (const float*)d_in[2];
    const float* out_w  = (const float*)d_in[3];
    const float* out_b  = (const float*)d_in[4];
    const float* dd     = (const float*)d_in[5];
    float* out = (float*)d_out;

    __nv_bfloat16 *xh, *xl, *wqh, *wql, *owh, *owl, *qkvh, *qkvl, *ath, *atl;
    cudaGetSymbolAddress((void**)&xh,  g_xh);  cudaGetSymbolAddress((void**)&xl,  g_xl);
    cudaGetSymbolAddress((void**)&wqh, g_wqh); cudaGetSymbolAddress((void**)&wql, g_wql);
    cudaGetSymbolAddress((void**)&owh, g_owh); cudaGetSymbolAddress((void**)&owl, g_owl);
    cudaGetSymbolAddress((void**)&qkvh, g_qkvh); cudaGetSymbolAddress((void**)&qkvl, g_qkvl);
    cudaGetSymbolAddress((void**)&ath, g_ath); cudaGetSymbolAddress((void**)&atl, g_atl);

    cudaFuncSetAttribute(gemm_tc, cudaFuncAttributeMaxDynamicSharedMemorySize,
                         GEMM_SMEM);
    cudaFuncSetAttribute(attn_tc, cudaFuncAttributeMaxDynamicSharedMemorySize,
                         ATTN_SMEM);

    // 0. split inputs/weights to bf16 hi/lo
    split_bf16<<<(M_ * E_ / 4 + 255) / 256, 256>>>(x, xh, xl, M_ * E_ / 4);
    split_bf16<<<(E3_ * E_ / 4 + 255) / 256, 256>>>(Wqkv_w, wqh, wql, E3_ * E_ / 4);
    split_bf16<<<(E_ * E_ / 4 + 255) / 256, 256>>>(out_w, owh, owl, E_ * E_ / 4);

    // 1. QKV projection -> split bf16 qkv
    gemm_tc<<<dim3(E3_ / 128, M_ / 128), 128, GEMM_SMEM>>>(
        xh, xl, wqh, wql, Wqkv_b, nullptr, qkvh, qkvl, M_, E3_, E_);

    // 2. attention -> split bf16 attn out
    attn_tc<<<dim3(S_ / 128, H_, B_), 256, ATTN_SMEM>>>(qkvh, qkvl, dd, ath, atl);

    // 3. output projection -> fp32 out
    gemm_tc<<<dim3(E_ / 128, M_ / 128), 128, GEMM_SMEM>>>(
        ath, atl, owh, owl, out_b, out, nullptr, nullptr, M_, E_, E_);
}